// round 8
// baseline (speedup 1.0000x reference)
#include <cuda_runtime.h>
#include <cuda_bf16.h>
#include <math.h>
#include <stdint.h>

#define Bc    8
#define Hc    128
#define Wc    128
#define Dc    256
#define Nc    8192
#define THREADS 256

// activation strides (bf16 elements per row)
#define KSA  136            // stage buffers: 128 k + 8 pad (272B = 17*16B, odd -> no ldsm conflicts)
#define KSPE 72             // PE buffer: 64 k + 8 pad

// SMEM byte offsets
#define ST0_HI   0          // 64*136*2 = 17408
#define ST0_LO   17408
#define ST1_HI   34816
#define ST1_LO   52224
#define PE_HI    69632      // 64*72*2 = 9216
#define PE_LO    78848
#define SM_METAO 88064      // 3*64*4 int
#define SM_METAW 91136      // 3*64*4 float
#define SM_GAMMA 94208      // 256 f32
#define SM_BETA  95232
#define SM_BIAS  96256      // 4*256 f32
#define SM_OW    100352     // 771 f32
#define SM_PSUM  103440     // 64*3 f32
#define SM_TOTAL 104256

// ---------------- device scratch ----------------
__device__ float g_t1[Bc * Hc * 64 * Dc];
__device__ float g_l1[Bc * 64 * 64 * Dc];
__device__ float g_t2[Bc * Hc * 32 * Dc];
__device__ float g_l2[Bc * 32 * 32 * Dc];
__device__ float g_film[Bc * 512];
// fragment-packed weights: [kb][n8 group][lane] -> {bh0, bh1, bl0, bl1}
__device__ __align__(16) uint4 g_w0f[52 * 32 * 32];      // layer0, K padded to 832
__device__ __align__(16) uint4 g_hwf[3 * 16 * 32 * 32];  // hidden layers

// ---------------- helpers ----------------
__device__ __forceinline__ uint32_t smem_u32(const void* p) {
    uint32_t a;
    asm("{ .reg .u64 t; cvta.to.shared.u64 t, %1; cvt.u32.u64 %0, t; }" : "=r"(a) : "l"(p));
    return a;
}
__device__ __forceinline__ void ldm4(uint32_t* r, uint32_t addr) {
    asm volatile("ldmatrix.sync.aligned.m8n8.x4.shared.b16 {%0,%1,%2,%3}, [%4];"
        : "=r"(r[0]), "=r"(r[1]), "=r"(r[2]), "=r"(r[3]) : "r"(addr));
}
__device__ __forceinline__ void mma16816(float* c, const uint32_t* a, uint32_t b0, uint32_t b1) {
    asm volatile("mma.sync.aligned.m16n8k16.row.col.f32.bf16.bf16.f32 "
        "{%0,%1,%2,%3}, {%4,%5,%6,%7}, {%8,%9}, {%0,%1,%2,%3};"
        : "+f"(c[0]), "+f"(c[1]), "+f"(c[2]), "+f"(c[3])
        : "r"(a[0]), "r"(a[1]), "r"(a[2]), "r"(a[3]), "r"(b0), "r"(b1));
}
__device__ __forceinline__ uint32_t pack_hi(float x, float y) {
    __nv_bfloat162 v(__float2bfloat16(x), __float2bfloat16(y));
    return *(uint32_t*)&v;
}
__device__ __forceinline__ uint32_t pack_lo(float x, float y) {
    float hx = __bfloat162float(__float2bfloat16(x));
    float hy = __bfloat162float(__float2bfloat16(y));
    __nv_bfloat162 v(__float2bfloat16(x - hx), __float2bfloat16(y - hy));
    return *(uint32_t*)&v;
}
__device__ __forceinline__ float gelu_t(float x) {
    float x3 = x * x * x;
    float t = tanhf(0.7978845608028654f * (x + 0.044715f * x3));
    return 0.5f * x * (1.0f + t);
}

// ---------------- resize (antialiased triangle, separable) ----------------
template <int INV, int HL, int WIN>
__device__ __forceinline__ void resize_w_body(const float* __restrict__ in, float* __restrict__ out) {
    const int WOUT = WIN / INV, NT = 2 * INV;
    int idx = blockIdx.x * blockDim.x + threadIdx.x;
    if (idx >= Bc * HL * WOUT * 64) return;
    int d4 = idx & 63, t = idx >> 6;
    int xo = t % WOUT; t /= WOUT;
    int y = t % HL, b = t / HL;
    float sf = (xo + 0.5f) * INV - 0.5f;
    int j0 = INV * xo - (INV / 2);
    float w[NT], wsum = 0.f;
#pragma unroll
    for (int i = 0; i < NT; i++) {
        int j = j0 + i;
        float ww = 1.0f - fabsf((float)j - sf) * (1.0f / INV);
        ww = (j >= 0 && j < WIN) ? fmaxf(ww, 0.f) : 0.f;
        w[i] = ww; wsum += ww;
    }
    float inv = 1.0f / wsum;
    const float4* ip = (const float4*)in + ((size_t)(b * HL + y) * WIN) * 64 + d4;
    float4 acc = make_float4(0.f, 0.f, 0.f, 0.f);
#pragma unroll
    for (int i = 0; i < NT; i++)
        if (w[i] > 0.f) {
            float4 v = __ldg(&ip[(j0 + i) * 64]);
            float ww = w[i] * inv;
            acc.x += ww * v.x; acc.y += ww * v.y; acc.z += ww * v.z; acc.w += ww * v.w;
        }
    ((float4*)out)[((size_t)(b * HL + y) * WOUT + xo) * 64 + d4] = acc;
}
template <int INV, int HIN, int WL>
__device__ __forceinline__ void resize_h_body(const float* __restrict__ in, float* __restrict__ out) {
    const int HOUT = HIN / INV, NT = 2 * INV;
    int idx = blockIdx.x * blockDim.x + threadIdx.x;
    if (idx >= Bc * HOUT * WL * 64) return;
    int d4 = idx & 63, t = idx >> 6;
    int x = t % WL; t /= WL;
    int yo = t % HOUT, b = t / HOUT;
    float sf = (yo + 0.5f) * INV - 0.5f;
    int j0 = INV * yo - (INV / 2);
    float w[NT], wsum = 0.f;
#pragma unroll
    for (int i = 0; i < NT; i++) {
        int j = j0 + i;
        float ww = 1.0f - fabsf((float)j - sf) * (1.0f / INV);
        ww = (j >= 0 && j < HIN) ? fmaxf(ww, 0.f) : 0.f;
        w[i] = ww; wsum += ww;
    }
    float inv = 1.0f / wsum;
    const float4* ip = (const float4*)in + ((size_t)b * HIN * WL + x) * 64 + d4;
    float4 acc = make_float4(0.f, 0.f, 0.f, 0.f);
#pragma unroll
    for (int i = 0; i < NT; i++)
        if (w[i] > 0.f) {
            float4 v = __ldg(&ip[(size_t)(j0 + i) * WL * 64]);
            float ww = w[i] * inv;
            acc.x += ww * v.x; acc.y += ww * v.y; acc.z += ww * v.z; acc.w += ww * v.w;
        }
    ((float4*)out)[((size_t)(b * HOUT + yo) * WL + x) * 64 + d4] = acc;
}
__global__ void resize_w2_kernel(const float* __restrict__ in) { resize_w_body<2, Hc, Wc>(in, g_t1); }
__global__ void resize_h2_kernel() { resize_h_body<2, Hc, 64>(g_t1, g_l1); }
__global__ void resize_w4_kernel(const float* __restrict__ in) { resize_w_body<4, Hc, Wc>(in, g_t2); }
__global__ void resize_h4_kernel() { resize_h_body<4, Hc, 32>(g_t2, g_l2); }

// ---------------- FiLM ----------------
__global__ void film_kernel(const float* __restrict__ cv, const float* __restrict__ cw,
                            const float* __restrict__ cb) {
    int b = blockIdx.x, j = threadIdx.x;
    float acc = cb[j];
    for (int k = 0; k < Dc; k++) acc = fmaf(cv[b * Dc + k], cw[k * 512 + j], acc);
    g_film[b * 512 + j] = acc;
}

// ---------------- weight prep: fragment packing + hi/lo split ----------------
__device__ __forceinline__ float w0val(const float* __restrict__ w0, int kp, int n) {
    if (kp >= 813) return 0.f;
    int orig;
    if (kp < 768) orig = 42 + (kp >> 8) * 256 + (kp & 255);
    else if (kp < 810) orig = kp - 768;
    else orig = kp;
    return w0[orig * 256 + n];
}

__global__ void prep_w0f(const float* __restrict__ w0) {
    int idx = blockIdx.x * blockDim.x + threadIdx.x;
    if (idx >= 52 * 32 * 32) return;
    int lane = idx & 31, nq = (idx >> 5) & 31, kb = idx >> 10;
    int g = lane >> 2, t = lane & 3;
    int row = nq * 8 + g;
    int k0 = kb * 16 + 2 * t;
    float v0 = w0val(w0, k0, row),     v1 = w0val(w0, k0 + 1, row);
    float v2 = w0val(w0, k0 + 8, row), v3 = w0val(w0, k0 + 9, row);
    g_w0f[idx] = make_uint4(pack_hi(v0, v1), pack_hi(v2, v3),
                            pack_lo(v0, v1), pack_lo(v2, v3));
}
__global__ void prep_hwf(const float* __restrict__ hw) {
    int idx = blockIdx.x * blockDim.x + threadIdx.x;
    if (idx >= 3 * 16 * 32 * 32) return;
    int lane = idx & 31, nq = (idx >> 5) & 31, kb = (idx >> 10) & 15, L = idx >> 14;
    int g = lane >> 2, t = lane & 3;
    int row = nq * 8 + g;
    int k0 = kb * 16 + 2 * t;
    const float* W = hw + (size_t)L * 65536;
    float v0 = W[k0 * 256 + row],       v1 = W[(k0 + 1) * 256 + row];
    float v2 = W[(k0 + 8) * 256 + row], v3 = W[(k0 + 9) * 256 + row];
    g_hwf[idx] = make_uint4(pack_hi(v0, v1), pack_hi(v2, v3),
                            pack_lo(v0, v1), pack_lo(v2, v3));
}

// ---------------- fused kernel ----------------
// PF_GATHER: one prefetch step (per thread) of half-chunk HC1 into stage DSTHI/DSTLO.
// Uses loop variable `kbi` (0..7) as the step index.
#define PF_GATHER(HC1, DSTHI, DSTLO) do {                                        \
    int lv_ = (HC1) >> 1, hf_ = (HC1) & 1;                                       \
    const float4* src_ = (lv_ == 0) ? (const float4*)grid                        \
                       : (lv_ == 1 ? (const float4*)g_l1 : (const float4*)g_l2); \
    int s_ = tid >> 2, q_ = tid & 3;                                             \
    const int* mo_ = (const int*)(sm + SM_METAO) + (lv_ * 64 + s_) * 4;          \
    const float* mw_ = (const float*)(sm + SM_METAW) + (lv_ * 64 + s_) * 4;      \
    int d4_ = hf_ * 32 + q_ * 8 + kbi;                                           \
    float4 A_ = __ldg(&src_[mo_[0] + d4_]);                                      \
    float4 B_ = __ldg(&src_[mo_[1] + d4_]);                                      \
    float4 C_ = __ldg(&src_[mo_[2] + d4_]);                                      \
    float4 D_ = __ldg(&src_[mo_[3] + d4_]);                                      \
    float w0_ = mw_[0], w1_ = mw_[1], w2_ = mw_[2], w3_ = mw_[3];                \
    float vx_ = w0_ * A_.x + w1_ * B_.x + w2_ * C_.x + w3_ * D_.x;               \
    float vy_ = w0_ * A_.y + w1_ * B_.y + w2_ * C_.y + w3_ * D_.y;               \
    float vz_ = w0_ * A_.z + w1_ * B_.z + w2_ * C_.z + w3_ * D_.z;               \
    float vw_ = w0_ * A_.w + w1_ * B_.w + w2_ * C_.w + w3_ * D_.w;               \
    int off_ = (s_ * KSA + (q_ * 8 + kbi) * 4) * 2;                              \
    *(uint2*)(sm + (DSTHI) + off_) = make_uint2(pack_hi(vx_, vy_), pack_hi(vz_, vw_)); \
    *(uint2*)(sm + (DSTLO) + off_) = make_uint2(pack_lo(vx_, vy_), pack_lo(vz_, vw_)); \
} while (0)

// per 16-K block: 4 ldmatrix + 8 coalesced LDG.128 + 48 HMMA (+ optional PF step)
#define KLOOP(AHI, ALO, ASTR, FRAG, NKB, KB0, PF)                                \
    _Pragma("unroll 2")                                                          \
    for (int kbi = 0; kbi < (NKB); kbi++) {                                      \
        uint32_t ah0[4], ah1[4], al0[4], al1[4];                                 \
        uint32_t arow = (uint32_t)(((mrow + (lane & 15)) * (ASTR) + kbi * 16 +   \
                                    ((lane >> 4) << 3)) * 2);                    \
        ldm4(ah0, smb + (AHI) + arow);                                           \
        ldm4(ah1, smb + (AHI) + arow + 16 * (ASTR) * 2);                         \
        ldm4(al0, smb + (ALO) + arow);                                           \
        ldm4(al1, smb + (ALO) + arow + 16 * (ASTR) * 2);                         \
        PF;                                                                      \
        const uint4* wf = (FRAG) + ((size_t)((KB0) + kbi) * 32 + (ncol >> 3)) * 32 + lane; \
        _Pragma("unroll")                                                        \
        for (int ns = 0; ns < 8; ns++) {                                         \
            uint4 f = __ldg(wf + ns * 32);                                       \
            mma16816(acc[0][ns], ah0, f.x, f.y);                                 \
            mma16816(acc[0][ns], ah0, f.z, f.w);                                 \
            mma16816(acc[0][ns], al0, f.x, f.y);                                 \
            mma16816(acc[1][ns], ah1, f.x, f.y);                                 \
            mma16816(acc[1][ns], ah1, f.z, f.w);                                 \
            mma16816(acc[1][ns], al1, f.x, f.y);                                 \
        }                                                                        \
    }

__global__ void __launch_bounds__(THREADS, 2)
fused_kernel(const float* __restrict__ grid,
             const float* __restrict__ coords,
             const float* __restrict__ oracle,
             const float* __restrict__ b0, const float* __restrict__ hb,
             const float* __restrict__ ow, const float* __restrict__ ob,
             float* __restrict__ out) {
    extern __shared__ char sm[];
    uint32_t smb = smem_u32(sm);
    float* smf = (float*)sm;
    int tid = threadIdx.x;
    int lane = tid & 31;
    int w = tid >> 5;
    int blk = blockIdx.x;
    int b = blk >> 7;               // 128 tiles of 64 per batch
    int n0 = (blk & 127) * 64;
    int mrow = (w & 1) * 32;        // warp M offset
    int ncol = (w >> 1) * 64;       // warp N offset
    int g = lane >> 2, t = lane & 3;

    // film / biases / out weights / psum init
    smf[(SM_GAMMA >> 2) + tid] = g_film[b * 512 + tid] + 1.0f;
    smf[(SM_BETA >> 2) + tid] = g_film[b * 512 + 256 + tid];
    smf[(SM_BIAS >> 2) + tid] = b0[tid];
#pragma unroll
    for (int l = 0; l < 3; l++)
        smf[(SM_BIAS >> 2) + 256 + l * 256 + tid] = hb[l * 256 + tid];
    for (int i = tid; i < 771; i += THREADS)
        smf[(SM_OW >> 2) + i] = (i < 768) ? ow[i] : ob[i - 768];
    if (tid < 192) smf[(SM_PSUM >> 2) + tid] = 0.f;

    // bilinear metadata: 3 levels x 64 samples
    if (tid < 192) {
        int lvl = tid >> 6, s = tid & 63;
        int n = n0 + s;
        int Hl = Hc >> lvl, Wl = Wc >> lvl;
        float c0 = coords[2 * n], c1 = coords[2 * n + 1];
        float y = (c0 + 1.0f) * 0.5f * (Hl - 1);
        float x = (c1 + 1.0f) * 0.5f * (Wl - 1);
        float y0f = fminf(fmaxf(floorf(y), 0.f), (float)(Hl - 1));
        float x0f = fminf(fmaxf(floorf(x), 0.f), (float)(Wl - 1));
        int y0 = (int)y0f, x0 = (int)x0f;
        int y1 = min(y0 + 1, Hl - 1), x1 = min(x0 + 1, Wl - 1);
        float wy = y - y0f, wx = x - x0f;
        int base = b * Hl * Wl;
        int* mo = (int*)(sm + SM_METAO) + tid * 4;
        float* mw = (float*)(sm + SM_METAW) + tid * 4;
        mo[0] = (base + y0 * Wl + x0) * 64;
        mo[1] = (base + y0 * Wl + x1) * 64;
        mo[2] = (base + y1 * Wl + x0) * 64;
        mo[3] = (base + y1 * Wl + x1) * 64;
        mw[0] = (1.f - wy) * (1.f - wx);
        mw[1] = (1.f - wy) * wx;
        mw[2] = wy * (1.f - wx);
        mw[3] = wy * wx;
    }
    __syncthreads();

    // ---- prologue: PE + oracle into PE buffer; gather half-chunk 0 into stage0 ----
    if (tid < 64) {
        int s = tid, n = n0 + s;
        float a[64];
        float c0v = coords[2 * n], c1v = coords[2 * n + 1];
        a[0] = c0v; a[1] = c1v;
        float pf = 3.14159265358979323846f;
#pragma unroll
        for (int f = 0; f < 10; f++) {
            float s0, q0, s1, q1;
            sincosf(c0v * pf, &s0, &q0);
            sincosf(c1v * pf, &s1, &q1);
            a[2 + 4 * f + 0] = s0; a[2 + 4 * f + 1] = s1;
            a[2 + 4 * f + 2] = q0; a[2 + 4 * f + 3] = q1;
            pf *= 2.0f;
        }
#pragma unroll
        for (int j = 0; j < 3; j++)
            a[42 + j] = oracle[((size_t)b * Nc + n) * 3 + j];
#pragma unroll
        for (int j = 45; j < 64; j++) a[j] = 0.f;
#pragma unroll
        for (int i = 0; i < 16; i++) {
            int off = (s * KSPE + i * 4) * 2;
            *(uint2*)(sm + PE_HI + off) =
                make_uint2(pack_hi(a[4 * i], a[4 * i + 1]), pack_hi(a[4 * i + 2], a[4 * i + 3]));
            *(uint2*)(sm + PE_LO + off) =
                make_uint2(pack_lo(a[4 * i], a[4 * i + 1]), pack_lo(a[4 * i + 2], a[4 * i + 3]));
        }
    }
    for (int kbi = 0; kbi < 8; kbi++) PF_GATHER(0, ST0_HI, ST0_LO);

    float acc[2][8][4];
#pragma unroll
    for (int mt = 0; mt < 2; mt++)
#pragma unroll
        for (int ns = 0; ns < 8; ns++)
#pragma unroll
            for (int i = 0; i < 4; i++) acc[mt][ns][i] = 0.f;

    // ---- layer 0: 6 pipelined half-chunks + PE chunk ----
    for (int hc = 0; hc < 6; hc++) {
        __syncthreads();
        int ahi = (hc & 1) ? ST1_HI : ST0_HI;
        int alo = (hc & 1) ? ST1_LO : ST0_LO;
        int dhi = (hc & 1) ? ST0_HI : ST1_HI;
        int dlo = (hc & 1) ? ST0_LO : ST1_LO;
        if (hc < 5) {
            KLOOP(ahi, alo, KSA, g_w0f, 8, hc * 8, PF_GATHER(hc + 1, dhi, dlo))
        } else {
            KLOOP(ahi, alo, KSA, g_w0f, 8, hc * 8, ((void)0))
        }
    }
    KLOOP(PE_HI, PE_LO, KSPE, g_w0f, 4, 48, ((void)0))

    // ---- hidden layers ----
    const float* gam = smf + (SM_GAMMA >> 2);
    const float* bet = smf + (SM_BETA >> 2);
    int sthi = (ncol & 128) ? ST1_HI : ST0_HI;
    int stlo = (ncol & 128) ? ST1_LO : ST0_LO;
    int ncl = ncol & 127;
    for (int L = 0; L < 3; L++) {
        const float* bias = smf + (SM_BIAS >> 2) + L * 256;
#pragma unroll
        for (int mt = 0; mt < 2; mt++)
#pragma unroll
            for (int ns = 0; ns < 8; ns++) {
                int nn0 = ncol + ns * 8 + 2 * t, nn1 = nn0 + 1;
                float ga0 = gam[nn0], ga1 = gam[nn1];
                float be0 = bet[nn0], be1 = bet[nn1];
                float bi0 = bias[nn0], bi1 = bias[nn1];
                acc[mt][ns][0] = gelu_t((acc[mt][ns][0] + bi0) * ga0 + be0);
                acc[mt][ns][1] = gelu_t((acc[mt][ns][1] + bi1) * ga1 + be1);
                acc[mt][ns][2] = gelu_t((acc[mt][ns][2] + bi0) * ga0 + be0);
                acc[mt][ns][3] = gelu_t((acc[mt][ns][3] + bi1) * ga1 + be1);
            }
        __syncthreads();
#pragma unroll
        for (int mt = 0; mt < 2; mt++)
#pragma unroll
            for (int ns = 0; ns < 8; ns++) {
                int nnl = ncl + ns * 8 + 2 * t;
                int r0 = mrow + mt * 16 + g, r1 = r0 + 8;
                *(uint32_t*)(sm + sthi + (r0 * KSA + nnl) * 2) = pack_hi(acc[mt][ns][0], acc[mt][ns][1]);
                *(uint32_t*)(sm + stlo + (r0 * KSA + nnl) * 2) = pack_lo(acc[mt][ns][0], acc[mt][ns][1]);
                *(uint32_t*)(sm + sthi + (r1 * KSA + nnl) * 2) = pack_hi(acc[mt][ns][2], acc[mt][ns][3]);
                *(uint32_t*)(sm + stlo + (r1 * KSA + nnl) * 2) = pack_lo(acc[mt][ns][2], acc[mt][ns][3]);
#pragma unroll
                for (int i = 0; i < 4; i++) acc[mt][ns][i] = 0.f;
            }
        __syncthreads();
        KLOOP(ST0_HI, ST0_LO, KSA, g_hwf + (size_t)L * 16384, 8, 0, ((void)0))
        KLOOP(ST1_HI, ST1_LO, KSA, g_hwf + (size_t)L * 16384, 8, 8, ((void)0))
    }

    // ---- output layer ----
    {
        const float* bias = smf + (SM_BIAS >> 2) + 3 * 256;
        const float* oww = smf + (SM_OW >> 2);
        float p[4][3];
#pragma unroll
        for (int i = 0; i < 4; i++) p[i][0] = p[i][1] = p[i][2] = 0.f;
#pragma unroll
        for (int mt = 0; mt < 2; mt++)
#pragma unroll
            for (int ns = 0; ns < 8; ns++) {
                int nn0 = ncol + ns * 8 + 2 * t, nn1 = nn0 + 1;
                float ga0 = gam[nn0], ga1 = gam[nn1];
                float be0 = bet[nn0], be1 = bet[nn1];
                float bi0 = bias[nn0], bi1 = bias[nn1];
                float v0 = gelu_t((acc[mt][ns][0] + bi0) * ga0 + be0);
                float v1 = gelu_t((acc[mt][ns][1] + bi1) * ga1 + be1);
                float v2 = gelu_t((acc[mt][ns][2] + bi0) * ga0 + be0);
                float v3 = gelu_t((acc[mt][ns][3] + bi1) * ga1 + be1);
#pragma unroll
                for (int o = 0; o < 3; o++) {
                    float w0o = oww[nn0 * 3 + o], w1o = oww[nn1 * 3 + o];
                    p[mt * 2 + 0][o] += v0 * w0o + v1 * w1o;
                    p[mt * 2 + 1][o] += v2 * w0o + v3 * w1o;
                }
            }
#pragma unroll
        for (int i = 0; i < 4; i++)
#pragma unroll
            for (int o = 0; o < 3; o++) {
                p[i][o] += __shfl_xor_sync(0xffffffffu, p[i][o], 1);
                p[i][o] += __shfl_xor_sync(0xffffffffu, p[i][o], 2);
            }
        if (t == 0) {
#pragma unroll
            for (int mt = 0; mt < 2; mt++) {
                int r0 = mrow + mt * 16 + g, r1 = r0 + 8;
#pragma unroll
                for (int o = 0; o < 3; o++) {
                    atomicAdd(smf + (SM_PSUM >> 2) + r0 * 3 + o, p[mt * 2 + 0][o]);
                    atomicAdd(smf + (SM_PSUM >> 2) + r1 * 3 + o, p[mt * 2 + 1][o]);
                }
            }
        }
    }
    __syncthreads();
    if (tid < 64) {
        const float* obv = smf + (SM_OW >> 2) + 768;
#pragma unroll
        for (int o = 0; o < 3; o++)
            out[((size_t)b * Nc + n0 + tid) * 3 + o] =
                tanhf(smf[(SM_PSUM >> 2) + tid * 3 + o] + obv[o]);
    }
}

// ---------------- launch ----------------
extern "C" void kernel_launch(void* const* d_in, const int* in_sizes, int n_in,
                              void* d_out, int out_size) {
    const float* grid   = (const float*)d_in[0];
    const float* cv     = (const float*)d_in[1];
    const float* coords = (const float*)d_in[2];
    const float* oracle = (const float*)d_in[3];
    const float* w0     = (const float*)d_in[4];
    const float* b0     = (const float*)d_in[5];
    const float* hw     = (const float*)d_in[6];
    const float* hb     = (const float*)d_in[7];
    const float* cw     = (const float*)d_in[8];
    const float* cb     = (const float*)d_in[9];
    const float* ow     = (const float*)d_in[10];
    const float* ob     = (const float*)d_in[11];
    float* out = (float*)d_out;

    cudaFuncSetAttribute(fused_kernel, cudaFuncAttributeMaxDynamicSharedMemorySize, SM_TOTAL);

    resize_w2_kernel<<<(Bc * Hc * 64 * 64 + 255) / 256, 256>>>(grid);
    resize_h2_kernel<<<(Bc * 64 * 64 * 64 + 255) / 256, 256>>>();
    resize_w4_kernel<<<(Bc * Hc * 32 * 64 + 255) / 256, 256>>>(grid);
    resize_h4_kernel<<<(Bc * 32 * 32 * 64 + 255) / 256, 256>>>();
    film_kernel<<<Bc, 512>>>(cv, cw, cb);
    prep_w0f<<<(52 * 32 * 32 + 255) / 256, 256>>>(w0);
    prep_hwf<<<(3 * 16 * 32 * 32 + 255) / 256, 256>>>(hw);
    fused_kernel<<<Bc * Nc / 64, THREADS, SM_TOTAL>>>(grid, coords, oracle,
                                                      b0, hb, ow, ob, out);
}

// round 10
// speedup vs baseline: 1.0312x; 1.0312x over previous
#include <cuda_runtime.h>
#include <cuda_bf16.h>
#include <math.h>
#include <stdint.h>

#define Bc    8
#define Hc    128
#define Wc    128
#define Dc    256
#define Nc    8192
#define THREADS 256

// activation strides (bf16 elements per row)
#define KSA  136            // stage buffers: 128 k + 8 pad
#define KSPE 72             // PE buffer: 64 k + 8 pad

// SMEM byte offsets
#define ST0_HI   0          // 64*136*2 = 17408
#define ST0_LO   17408
#define ST1_HI   34816
#define ST1_LO   52224
#define PE_HI    69632      // 64*72*2 = 9216
#define PE_LO    78848
#define SM_METAO 88064      // 3*64*4 int
#define SM_METAW 91136      // 3*64*4 float
#define SM_GAMMA 94208      // 256 f32
#define SM_BETA  95232
#define SM_BIAS  96256      // 4*256 f32
#define SM_OW    100352     // 771 f32
#define SM_PSUM  103440     // 64*3 f32
#define SM_TOTAL 104256

// ---------------- device scratch ----------------
__device__ float g_t1[Bc * Hc * 64 * Dc];
__device__ float g_l1[Bc * 64 * 64 * Dc];
__device__ float g_t2[Bc * Hc * 32 * Dc];
__device__ float g_l2[Bc * 32 * 32 * Dc];
__device__ float g_film[Bc * 512];
// fragment-packed weights: [kb][n8 group][lane] -> {bh0, bh1, bl0, bl1}
__device__ __align__(16) uint4 g_w0f[52 * 32 * 32];      // layer0, K padded to 832
__device__ __align__(16) uint4 g_hwf[3 * 16 * 32 * 32];  // hidden layers

// ---------------- helpers ----------------
__device__ __forceinline__ uint32_t smem_u32(const void* p) {
    uint32_t a;
    asm("{ .reg .u64 t; cvta.to.shared.u64 t, %1; cvt.u32.u64 %0, t; }" : "=r"(a) : "l"(p));
    return a;
}
__device__ __forceinline__ void ldm4(uint32_t* r, uint32_t addr) {
    asm volatile("ldmatrix.sync.aligned.m8n8.x4.shared.b16 {%0,%1,%2,%3}, [%4];"
        : "=r"(r[0]), "=r"(r[1]), "=r"(r[2]), "=r"(r[3]) : "r"(addr));
}
__device__ __forceinline__ void mma16816(float* c, const uint32_t* a, uint32_t b0, uint32_t b1) {
    asm volatile("mma.sync.aligned.m16n8k16.row.col.f32.bf16.bf16.f32 "
        "{%0,%1,%2,%3}, {%4,%5,%6,%7}, {%8,%9}, {%0,%1,%2,%3};"
        : "+f"(c[0]), "+f"(c[1]), "+f"(c[2]), "+f"(c[3])
        : "r"(a[0]), "r"(a[1]), "r"(a[2]), "r"(a[3]), "r"(b0), "r"(b1));
}
__device__ __forceinline__ uint32_t pack_hi(float x, float y) {
    __nv_bfloat162 v(__float2bfloat16(x), __float2bfloat16(y));
    return *(uint32_t*)&v;
}
__device__ __forceinline__ uint32_t pack_lo(float x, float y) {
    float hx = __bfloat162float(__float2bfloat16(x));
    float hy = __bfloat162float(__float2bfloat16(y));
    __nv_bfloat162 v(__float2bfloat16(x - hx), __float2bfloat16(y - hy));
    return *(uint32_t*)&v;
}
__device__ __forceinline__ float gelu_t(float x) {
    float x3 = x * x * x;
    float t = tanhf(0.7978845608028654f * (x + 0.044715f * x3));
    return 0.5f * x * (1.0f + t);
}

// ---------------- resize (antialiased triangle, separable) ----------------
template <int INV, int HL, int WIN>
__device__ __forceinline__ void resize_w_body(const float* __restrict__ in, float* __restrict__ out) {
    const int WOUT = WIN / INV, NT = 2 * INV;
    int idx = blockIdx.x * blockDim.x + threadIdx.x;
    if (idx >= Bc * HL * WOUT * 64) return;
    int d4 = idx & 63, t = idx >> 6;
    int xo = t % WOUT; t /= WOUT;
    int y = t % HL, b = t / HL;
    float sf = (xo + 0.5f) * INV - 0.5f;
    int j0 = INV * xo - (INV / 2);
    float w[NT], wsum = 0.f;
#pragma unroll
    for (int i = 0; i < NT; i++) {
        int j = j0 + i;
        float ww = 1.0f - fabsf((float)j - sf) * (1.0f / INV);
        ww = (j >= 0 && j < WIN) ? fmaxf(ww, 0.f) : 0.f;
        w[i] = ww; wsum += ww;
    }
    float inv = 1.0f / wsum;
    const float4* ip = (const float4*)in + ((size_t)(b * HL + y) * WIN) * 64 + d4;
    float4 acc = make_float4(0.f, 0.f, 0.f, 0.f);
#pragma unroll
    for (int i = 0; i < NT; i++)
        if (w[i] > 0.f) {
            float4 v = __ldg(&ip[(j0 + i) * 64]);
            float ww = w[i] * inv;
            acc.x += ww * v.x; acc.y += ww * v.y; acc.z += ww * v.z; acc.w += ww * v.w;
        }
    ((float4*)out)[((size_t)(b * HL + y) * WOUT + xo) * 64 + d4] = acc;
}
template <int INV, int HIN, int WL>
__device__ __forceinline__ void resize_h_body(const float* __restrict__ in, float* __restrict__ out) {
    const int HOUT = HIN / INV, NT = 2 * INV;
    int idx = blockIdx.x * blockDim.x + threadIdx.x;
    if (idx >= Bc * HOUT * WL * 64) return;
    int d4 = idx & 63, t = idx >> 6;
    int x = t % WL; t /= WL;
    int yo = t % HOUT, b = t / HOUT;
    float sf = (yo + 0.5f) * INV - 0.5f;
    int j0 = INV * yo - (INV / 2);
    float w[NT], wsum = 0.f;
#pragma unroll
    for (int i = 0; i < NT; i++) {
        int j = j0 + i;
        float ww = 1.0f - fabsf((float)j - sf) * (1.0f / INV);
        ww = (j >= 0 && j < HIN) ? fmaxf(ww, 0.f) : 0.f;
        w[i] = ww; wsum += ww;
    }
    float inv = 1.0f / wsum;
    const float4* ip = (const float4*)in + ((size_t)b * HIN * WL + x) * 64 + d4;
    float4 acc = make_float4(0.f, 0.f, 0.f, 0.f);
#pragma unroll
    for (int i = 0; i < NT; i++)
        if (w[i] > 0.f) {
            float4 v = __ldg(&ip[(size_t)(j0 + i) * WL * 64]);
            float ww = w[i] * inv;
            acc.x += ww * v.x; acc.y += ww * v.y; acc.z += ww * v.z; acc.w += ww * v.w;
        }
    ((float4*)out)[((size_t)(b * HOUT + yo) * WL + x) * 64 + d4] = acc;
}
__global__ void resize_w2_kernel(const float* __restrict__ in) { resize_w_body<2, Hc, Wc>(in, g_t1); }
__global__ void resize_h2_kernel() { resize_h_body<2, Hc, 64>(g_t1, g_l1); }
__global__ void resize_w4_kernel(const float* __restrict__ in) { resize_w_body<4, Hc, Wc>(in, g_t2); }
__global__ void resize_h4_kernel() { resize_h_body<4, Hc, 32>(g_t2, g_l2); }

// ---------------- FiLM ----------------
__global__ void film_kernel(const float* __restrict__ cv, const float* __restrict__ cw,
                            const float* __restrict__ cb) {
    int b = blockIdx.x, j = threadIdx.x;
    float acc = cb[j];
    for (int k = 0; k < Dc; k++) acc = fmaf(cv[b * Dc + k], cw[k * 512 + j], acc);
    g_film[b * 512 + j] = acc;
}

// ---------------- weight prep: fragment packing + hi/lo split ----------------
__device__ __forceinline__ float w0val(const float* __restrict__ w0, int kp, int n) {
    if (kp >= 813) return 0.f;
    int orig;
    if (kp < 768) orig = 42 + (kp >> 8) * 256 + (kp & 255);
    else if (kp < 810) orig = kp - 768;
    else orig = kp;
    return w0[orig * 256 + n];
}

__global__ void prep_w0f(const float* __restrict__ w0) {
    int idx = blockIdx.x * blockDim.x + threadIdx.x;
    if (idx >= 52 * 32 * 32) return;
    int lane = idx & 31, nq = (idx >> 5) & 31, kb = idx >> 10;
    int g = lane >> 2, t = lane & 3;
    int row = nq * 8 + g;
    int k0 = kb * 16 + 2 * t;
    float v0 = w0val(w0, k0, row),     v1 = w0val(w0, k0 + 1, row);
    float v2 = w0val(w0, k0 + 8, row), v3 = w0val(w0, k0 + 9, row);
    g_w0f[idx] = make_uint4(pack_hi(v0, v1), pack_hi(v2, v3),
                            pack_lo(v0, v1), pack_lo(v2, v3));
}
__global__ void prep_hwf(const float* __restrict__ hw) {
    int idx = blockIdx.x * blockDim.x + threadIdx.x;
    if (idx >= 3 * 16 * 32 * 32) return;
    int lane = idx & 31, nq = (idx >> 5) & 31, kb = (idx >> 10) & 15, L = idx >> 14;
    int g = lane >> 2, t = lane & 3;
    int row = nq * 8 + g;
    int k0 = kb * 16 + 2 * t;
    const float* W = hw + (size_t)L * 65536;
    float v0 = W[k0 * 256 + row],       v1 = W[(k0 + 1) * 256 + row];
    float v2 = W[(k0 + 8) * 256 + row], v3 = W[(k0 + 9) * 256 + row];
    g_hwf[idx] = make_uint4(pack_hi(v0, v1), pack_hi(v2, v3),
                            pack_lo(v0, v1), pack_lo(v2, v3));
}

// ---------------- fused kernel macros ----------------
// Full gather step (prologue): load + interpolate + store, step kbi of half-chunk HC1.
#define PF_FULL(HC1, DSTHI, DSTLO) do {                                          \
    int lv_ = (HC1) >> 1, hf_ = (HC1) & 1;                                       \
    const float4* src_ = (lv_ == 0) ? (const float4*)grid                        \
                       : (lv_ == 1 ? (const float4*)g_l1 : (const float4*)g_l2); \
    int s_ = tid >> 2, q_ = tid & 3;                                             \
    const int* mo_ = (const int*)(sm + SM_METAO) + (lv_ * 64 + s_) * 4;          \
    const float* mw_ = (const float*)(sm + SM_METAW) + (lv_ * 64 + s_) * 4;      \
    int d4_ = hf_ * 32 + q_ * 8 + kbi;                                           \
    float4 A_ = __ldg(&src_[mo_[0] + d4_]);                                      \
    float4 B_ = __ldg(&src_[mo_[1] + d4_]);                                      \
    float4 C_ = __ldg(&src_[mo_[2] + d4_]);                                      \
    float4 D_ = __ldg(&src_[mo_[3] + d4_]);                                      \
    float w0_ = mw_[0], w1_ = mw_[1], w2_ = mw_[2], w3_ = mw_[3];                \
    float vx_ = w0_ * A_.x + w1_ * B_.x + w2_ * C_.x + w3_ * D_.x;               \
    float vy_ = w0_ * A_.y + w1_ * B_.y + w2_ * C_.y + w3_ * D_.y;               \
    float vz_ = w0_ * A_.z + w1_ * B_.z + w2_ * C_.z + w3_ * D_.z;               \
    float vw_ = w0_ * A_.w + w1_ * B_.w + w2_ * C_.w + w3_ * D_.w;               \
    int off_ = (s_ * KSA + (q_ * 8 + kbi) * 4) * 2;                              \
    *(uint2*)(sm + (DSTHI) + off_) = make_uint2(pack_hi(vx_, vy_), pack_hi(vz_, vw_)); \
    *(uint2*)(sm + (DSTLO) + off_) = make_uint2(pack_lo(vx_, vy_), pack_lo(vz_, vw_)); \
} while (0)

// plain KLOOP: per 16-K block: 4 ldmatrix + 8 coalesced LDG.128 + 48 HMMA
#define KLOOP(AHI, ALO, ASTR, FRAG, NKB, KB0)                                    \
    _Pragma("unroll 2")                                                          \
    for (int kbi = 0; kbi < (NKB); kbi++) {                                      \
        uint32_t ah0[4], ah1[4], al0[4], al1[4];                                 \
        uint32_t arow = (uint32_t)(((mrow + (lane & 15)) * (ASTR) + kbi * 16 +   \
                                    ((lane >> 4) << 3)) * 2);                    \
        ldm4(ah0, smb + (AHI) + arow);                                           \
        ldm4(ah1, smb + (AHI) + arow + 16 * (ASTR) * 2);                         \
        ldm4(al0, smb + (ALO) + arow);                                           \
        ldm4(al1, smb + (ALO) + arow + 16 * (ASTR) * 2);                         \
        const uint4* wf = (FRAG) + ((size_t)((KB0) + kbi) * 32 + (ncol >> 3)) * 32 + lane; \
        _Pragma("unroll")                                                        \
        for (int ns = 0; ns < 8; ns++) {                                         \
            uint4 f = __ldg(wf + ns * 32);                                       \
            mma16816(acc[0][ns], ah0, f.x, f.y);                                 \
            mma16816(acc[0][ns], ah0, f.z, f.w);                                 \
            mma16816(acc[0][ns], al0, f.x, f.y);                                 \
            mma16816(acc[1][ns], ah1, f.x, f.y);                                 \
            mma16816(acc[1][ns], ah1, f.z, f.w);                                 \
            mma16816(acc[1][ns], al1, f.x, f.y);                                 \
        }                                                                        \
    }

// pipelined KLOOP: prefetch LDGs issued BEFORE the HMMA block, consumed AFTER it.
#define KLOOP_PF(AHI, ALO, FRAG, KB0, HC1, DSTHI, DSTLO)                         \
    _Pragma("unroll 2")                                                          \
    for (int kbi = 0; kbi < 8; kbi++) {                                          \
        uint32_t ah0[4], ah1[4], al0[4], al1[4];                                 \
        uint32_t arow = (uint32_t)(((mrow + (lane & 15)) * KSA + kbi * 16 +      \
                                    ((lane >> 4) << 3)) * 2);                    \
        ldm4(ah0, smb + (AHI) + arow);                                           \
        ldm4(ah1, smb + (AHI) + arow + 16 * KSA * 2);                            \
        ldm4(al0, smb + (ALO) + arow);                                           \
        ldm4(al1, smb + (ALO) + arow + 16 * KSA * 2);                            \
        int lv_ = (HC1) >> 1, hf_ = (HC1) & 1;                                   \
        const float4* src_ = (lv_ == 0) ? (const float4*)grid                    \
                       : (lv_ == 1 ? (const float4*)g_l1 : (const float4*)g_l2); \
        int s_ = tid >> 2, q_ = tid & 3;                                         \
        const int* mo_ = (const int*)(sm + SM_METAO) + (lv_ * 64 + s_) * 4;      \
        int d4_ = hf_ * 32 + q_ * 8 + kbi;                                       \
        float4 A_ = __ldg(&src_[mo_[0] + d4_]);                                  \
        float4 B_ = __ldg(&src_[mo_[1] + d4_]);                                  \
        float4 C_ = __ldg(&src_[mo_[2] + d4_]);                                  \
        float4 D_ = __ldg(&src_[mo_[3] + d4_]);                                  \
        const uint4* wf = (FRAG) + ((size_t)((KB0) + kbi) * 32 + (ncol >> 3)) * 32 + lane; \
        _Pragma("unroll")                                                        \
        for (int ns = 0; ns < 8; ns++) {                                         \
            uint4 f = __ldg(wf + ns * 32);                                       \
            mma16816(acc[0][ns], ah0, f.x, f.y);                                 \
            mma16816(acc[0][ns], ah0, f.z, f.w);                                 \
            mma16816(acc[0][ns], al0, f.x, f.y);                                 \
            mma16816(acc[1][ns], ah1, f.x, f.y);                                 \
            mma16816(acc[1][ns], ah1, f.z, f.w);                                 \
            mma16816(acc[1][ns], al1, f.x, f.y);                                 \
        }                                                                        \
        const float* mw_ = (const float*)(sm + SM_METAW) + (lv_ * 64 + s_) * 4;  \
        float w0_ = mw_[0], w1_ = mw_[1], w2_ = mw_[2], w3_ = mw_[3];            \
        float vx_ = w0_ * A_.x + w1_ * B_.x + w2_ * C_.x + w3_ * D_.x;           \
        float vy_ = w0_ * A_.y + w1_ * B_.y + w2_ * C_.y + w3_ * D_.y;           \
        float vz_ = w0_ * A_.z + w1_ * B_.z + w2_ * C_.z + w3_ * D_.z;           \
        float vw_ = w0_ * A_.w + w1_ * B_.w + w2_ * C_.w + w3_ * D_.w;           \
        int off_ = (s_ * KSA + (q_ * 8 + kbi) * 4) * 2;                          \
        *(uint2*)(sm + (DSTHI) + off_) = make_uint2(pack_hi(vx_, vy_), pack_hi(vz_, vw_)); \
        *(uint2*)(sm + (DSTLO) + off_) = make_uint2(pack_lo(vx_, vy_), pack_lo(vz_, vw_)); \
    }

__global__ void __launch_bounds__(THREADS, 2)
fused_kernel(const float* __restrict__ grid,
             const float* __restrict__ coords,
             const float* __restrict__ oracle,
             const float* __restrict__ b0, const float* __restrict__ hb,
             const float* __restrict__ ow, const float* __restrict__ ob,
             float* __restrict__ out) {
    extern __shared__ char sm[];
    uint32_t smb = smem_u32(sm);
    float* smf = (float*)sm;
    int tid = threadIdx.x;
    int lane = tid & 31;
    int w = tid >> 5;
    int blk = blockIdx.x;
    int b = blk >> 7;               // 128 tiles of 64 per batch
    int n0 = (blk & 127) * 64;
    int mrow = (w & 1) * 32;        // warp M offset
    int ncol = (w >> 1) * 64;       // warp N offset
    int g = lane >> 2, t = lane & 3;

    // film / biases / out weights / psum init
    smf[(SM_GAMMA >> 2) + tid] = g_film[b * 512 + tid] + 1.0f;
    smf[(SM_BETA >> 2) + tid] = g_film[b * 512 + 256 + tid];
    smf[(SM_BIAS >> 2) + tid] = b0[tid];
#pragma unroll
    for (int l = 0; l < 3; l++)
        smf[(SM_BIAS >> 2) + 256 + l * 256 + tid] = hb[l * 256 + tid];
    for (int i = tid; i < 771; i += THREADS)
        smf[(SM_OW >> 2) + i] = (i < 768) ? ow[i] : ob[i - 768];
    if (tid < 192) smf[(SM_PSUM >> 2) + tid] = 0.f;

    // bilinear metadata: 3 levels x 64 samples
    if (tid < 192) {
        int lvl = tid >> 6, s = tid & 63;
        int n = n0 + s;
        int Hl = Hc >> lvl, Wl = Wc >> lvl;
        float c0 = coords[2 * n], c1 = coords[2 * n + 1];
        float y = (c0 + 1.0f) * 0.5f * (Hl - 1);
        float x = (c1 + 1.0f) * 0.5f * (Wl - 1);
        float y0f = fminf(fmaxf(floorf(y), 0.f), (float)(Hl - 1));
        float x0f = fminf(fmaxf(floorf(x), 0.f), (float)(Wl - 1));
        int y0 = (int)y0f, x0 = (int)x0f;
        int y1 = min(y0 + 1, Hl - 1), x1 = min(x0 + 1, Wl - 1);
        float wy = y - y0f, wx = x - x0f;
        int base = b * Hl * Wl;
        int* mo = (int*)(sm + SM_METAO) + tid * 4;
        float* mw = (float*)(sm + SM_METAW) + tid * 4;
        mo[0] = (base + y0 * Wl + x0) * 64;
        mo[1] = (base + y0 * Wl + x1) * 64;
        mo[2] = (base + y1 * Wl + x0) * 64;
        mo[3] = (base + y1 * Wl + x1) * 64;
        mw[0] = (1.f - wy) * (1.f - wx);
        mw[1] = (1.f - wy) * wx;
        mw[2] = wy * (1.f - wx);
        mw[3] = wy * wx;
    }
    __syncthreads();

    // ---- prologue: PE + oracle into PE buffer; gather half-chunk 0 into stage0 ----
    if (tid < 64) {
        int s = tid, n = n0 + s;
        float a[64];
        float c0v = coords[2 * n], c1v = coords[2 * n + 1];
        a[0] = c0v; a[1] = c1v;
        float pf = 3.14159265358979323846f;
#pragma unroll
        for (int f = 0; f < 10; f++) {
            float s0, q0, s1, q1;
            sincosf(c0v * pf, &s0, &q0);
            sincosf(c1v * pf, &s1, &q1);
            a[2 + 4 * f + 0] = s0; a[2 + 4 * f + 1] = s1;
            a[2 + 4 * f + 2] = q0; a[2 + 4 * f + 3] = q1;
            pf *= 2.0f;
        }
#pragma unroll
        for (int j = 0; j < 3; j++)
            a[42 + j] = oracle[((size_t)b * Nc + n) * 3 + j];
#pragma unroll
        for (int j = 45; j < 64; j++) a[j] = 0.f;
#pragma unroll
        for (int i = 0; i < 16; i++) {
            int off = (s * KSPE + i * 4) * 2;
            *(uint2*)(sm + PE_HI + off) =
                make_uint2(pack_hi(a[4 * i], a[4 * i + 1]), pack_hi(a[4 * i + 2], a[4 * i + 3]));
            *(uint2*)(sm + PE_LO + off) =
                make_uint2(pack_lo(a[4 * i], a[4 * i + 1]), pack_lo(a[4 * i + 2], a[4 * i + 3]));
        }
    }
#pragma unroll 2
    for (int kbi = 0; kbi < 8; kbi++) PF_FULL(0, ST0_HI, ST0_LO);

    float acc[2][8][4];
#pragma unroll
    for (int mt = 0; mt < 2; mt++)
#pragma unroll
        for (int ns = 0; ns < 8; ns++)
#pragma unroll
            for (int i = 0; i < 4; i++) acc[mt][ns][i] = 0.f;

    // ---- layer 0: 6 pipelined half-chunks + PE chunk ----
    __syncthreads();
    KLOOP_PF(ST0_HI, ST0_LO, g_w0f, 0, 1, ST1_HI, ST1_LO)
    __syncthreads();
    KLOOP_PF(ST1_HI, ST1_LO, g_w0f, 8, 2, ST0_HI, ST0_LO)
    __syncthreads();
    KLOOP_PF(ST0_HI, ST0_LO, g_w0f, 16, 3, ST1_HI, ST1_LO)
    __syncthreads();
    KLOOP_PF(ST1_HI, ST1_LO, g_w0f, 24, 4, ST0_HI, ST0_LO)
    __syncthreads();
    KLOOP_PF(ST0_HI, ST0_LO, g_w0f, 32, 5, ST1_HI, ST1_LO)
    __syncthreads();
    KLOOP(ST1_HI, ST1_LO, KSA, g_w0f, 8, 40)
    KLOOP(PE_HI, PE_LO, KSPE, g_w0f, 4, 48)

    // ---- hidden layers ----
    const float* gam = smf + (SM_GAMMA >> 2);
    const float* bet = smf + (SM_BETA >> 2);
    int sthi = (ncol & 128) ? ST1_HI : ST0_HI;
    int stlo = (ncol & 128) ? ST1_LO : ST0_LO;
    int ncl = ncol & 127;
    for (int L = 0; L < 3; L++) {
        const float* bias = smf + (SM_BIAS >> 2) + L * 256;
#pragma unroll
        for (int mt = 0; mt < 2; mt++)
#pragma unroll
            for (int ns = 0; ns < 8; ns++) {
                int nn0 = ncol + ns * 8 + 2 * t, nn1 = nn0 + 1;
                float ga0 = gam[nn0], ga1 = gam[nn1];
                float be0 = bet[nn0], be1 = bet[nn1];
                float bi0 = bias[nn0], bi1 = bias[nn1];
                acc[mt][ns][0] = gelu_t((acc[mt][ns][0] + bi0) * ga0 + be0);
                acc[mt][ns][1] = gelu_t((acc[mt][ns][1] + bi1) * ga1 + be1);
                acc[mt][ns][2] = gelu_t((acc[mt][ns][2] + bi0) * ga0 + be0);
                acc[mt][ns][3] = gelu_t((acc[mt][ns][3] + bi1) * ga1 + be1);
            }
        __syncthreads();
#pragma unroll
        for (int mt = 0; mt < 2; mt++)
#pragma unroll
            for (int ns = 0; ns < 8; ns++) {
                int nnl = ncl + ns * 8 + 2 * t;
                int r0 = mrow + mt * 16 + g, r1 = r0 + 8;
                *(uint32_t*)(sm + sthi + (r0 * KSA + nnl) * 2) = pack_hi(acc[mt][ns][0], acc[mt][ns][1]);
                *(uint32_t*)(sm + stlo + (r0 * KSA + nnl) * 2) = pack_lo(acc[mt][ns][0], acc[mt][ns][1]);
                *(uint32_t*)(sm + sthi + (r1 * KSA + nnl) * 2) = pack_hi(acc[mt][ns][2], acc[mt][ns][3]);
                *(uint32_t*)(sm + stlo + (r1 * KSA + nnl) * 2) = pack_lo(acc[mt][ns][2], acc[mt][ns][3]);
#pragma unroll
                for (int i = 0; i < 4; i++) acc[mt][ns][i] = 0.f;
            }
        __syncthreads();
        KLOOP(ST0_HI, ST0_LO, KSA, g_hwf + (size_t)L * 16384, 8, 0)
        KLOOP(ST1_HI, ST1_LO, KSA, g_hwf + (size_t)L * 16384, 8, 8)
    }

    // ---- output layer ----
    {
        const float* bias = smf + (SM_BIAS >> 2) + 3 * 256;
        const float* oww = smf + (SM_OW >> 2);
        float p[4][3];
#pragma unroll
        for (int i = 0; i < 4; i++) p[i][0] = p[i][1] = p[i][2] = 0.f;
#pragma unroll
        for (int mt = 0; mt < 2; mt++)
#pragma unroll
            for (int ns = 0; ns < 8; ns++) {
                int nn0 = ncol + ns * 8 + 2 * t, nn1 = nn0 + 1;
                float ga0 = gam[nn0], ga1 = gam[nn1];
                float be0 = bet[nn0], be1 = bet[nn1];
                float bi0 = bias[nn0], bi1 = bias[nn1];
                float v0 = gelu_t((acc[mt][ns][0] + bi0) * ga0 + be0);
                float v1 = gelu_t((acc[mt][ns][1] + bi1) * ga1 + be1);
                float v2 = gelu_t((acc[mt][ns][2] + bi0) * ga0 + be0);
                float v3 = gelu_t((acc[mt][ns][3] + bi1) * ga1 + be1);
#pragma unroll
                for (int o = 0; o < 3; o++) {
                    float w0o = oww[nn0 * 3 + o], w1o = oww[nn1 * 3 + o];
                    p[mt * 2 + 0][o] += v0 * w0o + v1 * w1o;
                    p[mt * 2 + 1][o] += v2 * w0o + v3 * w1o;
                }
            }
#pragma unroll
        for (int i = 0; i < 4; i++)
#pragma unroll
            for (int o = 0; o < 3; o++) {
                p[i][o] += __shfl_xor_sync(0xffffffffu, p[i][o], 1);
                p[i][o] += __shfl_xor_sync(0xffffffffu, p[i][o], 2);
            }
        if (t == 0) {
#pragma unroll
            for (int mt = 0; mt < 2; mt++) {
                int r0 = mrow + mt * 16 + g, r1 = r0 + 8;
#pragma unroll
                for (int o = 0; o < 3; o++) {
                    atomicAdd(smf + (SM_PSUM >> 2) + r0 * 3 + o, p[mt * 2 + 0][o]);
                    atomicAdd(smf + (SM_PSUM >> 2) + r1 * 3 + o, p[mt * 2 + 1][o]);
                }
            }
        }
    }
    __syncthreads();
    if (tid < 64) {
        const float* obv = smf + (SM_OW >> 2) + 768;
#pragma unroll
        for (int o = 0; o < 3; o++)
            out[((size_t)b * Nc + n0 + tid) * 3 + o] =
                tanhf(smf[(SM_PSUM >> 2) + tid * 3 + o] + obv[o]);
    }
}

// ---------------- launch ----------------
extern "C" void kernel_launch(void* const* d_in, const int* in_sizes, int n_in,
                              void* d_out, int out_size) {
    const float* grid   = (const float*)d_in[0];
    const float* cv     = (const float*)d_in[1];
    const float* coords = (const float*)d_in[2];
    const float* oracle = (const float*)d_in[3];
    const float* w0     = (const float*)d_in[4];
    const float* b0     = (const float*)d_in[5];
    const float* hw     = (const float*)d_in[6];
    const float* hb     = (const float*)d_in[7];
    const float* cw     = (const float*)d_in[8];
    const float* cb     = (const float*)d_in[9];
    const float* ow     = (const float*)d_in[10];
    const float* ob     = (const float*)d_in[11];
    float* out = (float*)d_out;

    cudaFuncSetAttribute(fused_kernel, cudaFuncAttributeMaxDynamicSharedMemorySize, SM_TOTAL);

    resize_w2_kernel<<<(Bc * Hc * 64 * 64 + 255) / 256, 256>>>(grid);
    resize_h2_kernel<<<(Bc * 64 * 64 * 64 + 255) / 256, 256>>>();
    resize_w4_kernel<<<(Bc * Hc * 32 * 64 + 255) / 256, 256>>>(grid);
    resize_h4_kernel<<<(Bc * 32 * 32 * 64 + 255) / 256, 256>>>();
    film_kernel<<<Bc, 512>>>(cv, cw, cb);
    prep_w0f<<<(52 * 32 * 32 + 255) / 256, 256>>>(w0);
    prep_hwf<<<(3 * 16 * 32 * 32 + 255) / 256, 256>>>(hw);
    fused_kernel<<<Bc * Nc / 64, THREADS, SM_TOTAL>>>(grid, coords, oracle,
                                                      b0, hb, ow, ob, out);
}

// round 13
// speedup vs baseline: 1.1178x; 1.0840x over previous
#include <cuda_runtime.h>
#include <cuda_bf16.h>
#include <math.h>
#include <stdint.h>

#define Bc    8
#define Hc    128
#define Wc    128
#define Dc    256
#define Nc    8192
#define THREADS 256

// SMEM byte offsets
#define KS       264            // bf16 stride per activation row (528B = 33*16B)
#define A_HI     0              // 64*264*2 = 33792
#define A_LO     33792
#define SM_METAO 67584          // 3*64*4 int
#define SM_METAW 70656          // 3*64*4 float
#define SM_GAMMA 73728          // 256 f32
#define SM_BETA  74752
#define SM_BIAS  75776          // 4*256 f32
#define SM_OW    79872          // 771 f32
#define SM_PSUM  82960          // 64*3 f32
#define SM_TOTAL 83776

// ---------------- device scratch ----------------
__device__ float g_l1[Bc * 64 * 64 * Dc];   // level1 (33 MB)
__device__ float g_l2[Bc * 32 * 32 * Dc];   // level2 (8 MB)
__device__ float g_film[Bc * 512];
// fragment-packed weights: [kb][n8 group][lane] -> {bh0, bh1, bl0, bl1}
__device__ __align__(16) uint4 g_w0f[52 * 32 * 32];      // layer0, K padded to 832
__device__ __align__(16) uint4 g_hwf[3 * 16 * 32 * 32];  // hidden layers

// ---------------- helpers ----------------
__device__ __forceinline__ uint32_t smem_u32(const void* p) {
    uint32_t a;
    asm("{ .reg .u64 t; cvta.to.shared.u64 t, %1; cvt.u32.u64 %0, t; }" : "=r"(a) : "l"(p));
    return a;
}
__device__ __forceinline__ void ldm4(uint32_t* r, uint32_t addr) {
    asm volatile("ldmatrix.sync.aligned.m8n8.x4.shared.b16 {%0,%1,%2,%3}, [%4];"
        : "=r"(r[0]), "=r"(r[1]), "=r"(r[2]), "=r"(r[3]) : "r"(addr));
}
__device__ __forceinline__ void mma16816(float* c, const uint32_t* a, uint32_t b0, uint32_t b1) {
    asm volatile("mma.sync.aligned.m16n8k16.row.col.f32.bf16.bf16.f32 "
        "{%0,%1,%2,%3}, {%4,%5,%6,%7}, {%8,%9}, {%0,%1,%2,%3};"
        : "+f"(c[0]), "+f"(c[1]), "+f"(c[2]), "+f"(c[3])
        : "r"(a[0]), "r"(a[1]), "r"(a[2]), "r"(a[3]), "r"(b0), "r"(b1));
}
__device__ __forceinline__ uint32_t pack_hi(float x, float y) {
    __nv_bfloat162 v(__float2bfloat16(x), __float2bfloat16(y));
    return *(uint32_t*)&v;
}
__device__ __forceinline__ uint32_t pack_lo(float x, float y) {
    float hx = __bfloat162float(__float2bfloat16(x));
    float hy = __bfloat162float(__float2bfloat16(y));
    __nv_bfloat162 v(__float2bfloat16(x - hx), __float2bfloat16(y - hy));
    return *(uint32_t*)&v;
}
__device__ __forceinline__ float gelu_t(float x) {
    float x3 = x * x * x;
    float t = tanhf(0.7978845608028654f * (x + 0.044715f * x3));
    return 0.5f * x * (1.0f + t);
}

// ---------------- direct 2D antialiased triangle resize ----------------
// out[b][yo][xo][:] = sum_{iy,ix} wy[iy]*wx[ix]*grid[b][jy][jx][:] / (sy*sx)
// identical math to separable two-pass with per-axis renormalization.
// NOTE: out is a __device__ symbol referenced from DEVICE code (host cannot
// pass a __device__ array address as a kernel argument).
template <int INV, int OUTW>
__device__ __forceinline__ void resize2d_body(const float* __restrict__ in,
                                              float* __restrict__ out) {
    const int NT = 2 * INV;
    int idx = blockIdx.x * blockDim.x + threadIdx.x;
    if (idx >= Bc * OUTW * OUTW * 64) return;
    int d4 = idx & 63;
    int t2 = idx >> 6;
    int xo = t2 % OUTW; t2 /= OUTW;
    int yo = t2 % OUTW;
    int b = t2 / OUTW;

    int jy0 = INV * yo - (INV / 2), jx0 = INV * xo - (INV / 2);
    float sfy = (yo + 0.5f) * INV - 0.5f, sfx = (xo + 0.5f) * INV - 0.5f;
    float wy[NT], wx[NT], sy = 0.f, sx = 0.f;
#pragma unroll
    for (int i = 0; i < NT; i++) {
        int jy = jy0 + i;
        float w = 1.0f - fabsf((float)jy - sfy) * (1.0f / INV);
        w = (jy >= 0 && jy < Hc) ? fmaxf(w, 0.f) : 0.f;
        wy[i] = w; sy += w;
        int jx = jx0 + i;
        float v = 1.0f - fabsf((float)jx - sfx) * (1.0f / INV);
        v = (jx >= 0 && jx < Wc) ? fmaxf(v, 0.f) : 0.f;
        wx[i] = v; sx += v;
    }
    float norm = 1.0f / (sy * sx);

    const float4* ip = (const float4*)in + (size_t)b * Hc * Wc * 64 + d4;
    float4 acc = make_float4(0.f, 0.f, 0.f, 0.f);
#pragma unroll
    for (int iy = 0; iy < NT; iy++) {
        if (wy[iy] <= 0.f) continue;
        const float4* rp = ip + (size_t)(jy0 + iy) * Wc * 64;
#pragma unroll
        for (int ix = 0; ix < NT; ix++) {
            if (wx[ix] <= 0.f) continue;
            float4 v = __ldg(rp + (jx0 + ix) * 64);
            float w = wy[iy] * wx[ix];
            acc.x += w * v.x; acc.y += w * v.y; acc.z += w * v.z; acc.w += w * v.w;
        }
    }
    ((float4*)out)[((size_t)(b * OUTW + yo) * OUTW + xo) * 64 + d4] =
        make_float4(acc.x * norm, acc.y * norm, acc.z * norm, acc.w * norm);
}

__global__ void resize2d_l1_kernel(const float* __restrict__ in) {
    resize2d_body<2, 64>(in, g_l1);
}
__global__ void resize2d_l2_kernel(const float* __restrict__ in) {
    resize2d_body<4, 32>(in, g_l2);
}

// ---------------- FiLM ----------------
__global__ void film_kernel(const float* __restrict__ cv, const float* __restrict__ cw,
                            const float* __restrict__ cb) {
    int b = blockIdx.x, j = threadIdx.x;
    float acc = cb[j];
    for (int k = 0; k < Dc; k++) acc = fmaf(cv[b * Dc + k], cw[k * 512 + j], acc);
    g_film[b * 512 + j] = acc;
}

// ---------------- weight prep: fragment packing + hi/lo split ----------------
__device__ __forceinline__ float w0val(const float* __restrict__ w0, int kp, int n) {
    if (kp >= 813) return 0.f;
    int orig;
    if (kp < 768) orig = 42 + (kp >> 8) * 256 + (kp & 255);
    else if (kp < 810) orig = kp - 768;
    else orig = kp;
    return w0[orig * 256 + n];
}

__global__ void prep_w0f(const float* __restrict__ w0) {
    int idx = blockIdx.x * blockDim.x + threadIdx.x;
    if (idx >= 52 * 32 * 32) return;
    int lane = idx & 31, nq = (idx >> 5) & 31, kb = idx >> 10;
    int g = lane >> 2, t = lane & 3;
    int row = nq * 8 + g;
    int k0 = kb * 16 + 2 * t;
    float v0 = w0val(w0, k0, row),     v1 = w0val(w0, k0 + 1, row);
    float v2 = w0val(w0, k0 + 8, row), v3 = w0val(w0, k0 + 9, row);
    g_w0f[idx] = make_uint4(pack_hi(v0, v1), pack_hi(v2, v3),
                            pack_lo(v0, v1), pack_lo(v2, v3));
}
__global__ void prep_hwf(const float* __restrict__ hw) {
    int idx = blockIdx.x * blockDim.x + threadIdx.x;
    if (idx >= 3 * 16 * 32 * 32) return;
    int lane = idx & 31, nq = (idx >> 5) & 31, kb = (idx >> 10) & 15, L = idx >> 14;
    int g = lane >> 2, t = lane & 3;
    int row = nq * 8 + g;
    int k0 = kb * 16 + 2 * t;
    const float* W = hw + (size_t)L * 65536;
    float v0 = W[k0 * 256 + row],       v1 = W[(k0 + 1) * 256 + row];
    float v2 = W[(k0 + 8) * 256 + row], v3 = W[(k0 + 9) * 256 + row];
    g_hwf[idx] = make_uint4(pack_hi(v0, v1), pack_hi(v2, v3),
                            pack_lo(v0, v1), pack_lo(v2, v3));
}

// ---------------- fused kernel ----------------
__global__ void __launch_bounds__(THREADS, 2)
fused_kernel(const float* __restrict__ grid,
             const float* __restrict__ coords,
             const float* __restrict__ oracle,
             const float* __restrict__ b0, const float* __restrict__ hb,
             const float* __restrict__ ow, const float* __restrict__ ob,
             float* __restrict__ out) {
    extern __shared__ char sm[];
    uint32_t smb = smem_u32(sm);
    float* smf = (float*)sm;
    int tid = threadIdx.x;
    int lane = tid & 31;
    int w = tid >> 5;
    int blk = blockIdx.x;
    int b = blk >> 7;               // 128 tiles of 64 per batch
    int n0 = (blk & 127) * 64;
    int mrow = (w & 1) * 32;        // warp M offset
    int ncol = (w >> 1) * 64;       // warp N offset
    int g = lane >> 2, t = lane & 3;

    // film / biases / out weights / psum init
    smf[(SM_GAMMA >> 2) + tid] = g_film[b * 512 + tid] + 1.0f;
    smf[(SM_BETA >> 2) + tid] = g_film[b * 512 + 256 + tid];
    smf[(SM_BIAS >> 2) + tid] = b0[tid];
#pragma unroll
    for (int l = 0; l < 3; l++)
        smf[(SM_BIAS >> 2) + 256 + l * 256 + tid] = hb[l * 256 + tid];
    for (int i = tid; i < 771; i += THREADS)
        smf[(SM_OW >> 2) + i] = (i < 768) ? ow[i] : ob[i - 768];
    if (tid < 192) smf[(SM_PSUM >> 2) + tid] = 0.f;

    // bilinear metadata: 3 levels x 64 samples
    if (tid < 192) {
        int lvl = tid >> 6, s = tid & 63;
        int n = n0 + s;
        int Hl = Hc >> lvl, Wl = Wc >> lvl;
        float c0 = coords[2 * n], c1 = coords[2 * n + 1];
        float y = (c0 + 1.0f) * 0.5f * (Hl - 1);
        float x = (c1 + 1.0f) * 0.5f * (Wl - 1);
        float y0f = fminf(fmaxf(floorf(y), 0.f), (float)(Hl - 1));
        float x0f = fminf(fmaxf(floorf(x), 0.f), (float)(Wl - 1));
        int y0 = (int)y0f, x0 = (int)x0f;
        int y1 = min(y0 + 1, Hl - 1), x1 = min(x0 + 1, Wl - 1);
        float wy = y - y0f, wx = x - x0f;
        int base = b * Hl * Wl;
        int* mo = (int*)(sm + SM_METAO) + tid * 4;
        float* mw = (float*)(sm + SM_METAW) + tid * 4;
        mo[0] = (base + y0 * Wl + x0) * 64;
        mo[1] = (base + y0 * Wl + x1) * 64;
        mo[2] = (base + y1 * Wl + x0) * 64;
        mo[3] = (base + y1 * Wl + x1) * 64;
        mw[0] = (1.f - wy) * (1.f - wx);
        mw[1] = (1.f - wy) * wx;
        mw[2] = wy * (1.f - wx);
        mw[3] = wy * wx;
    }
    __syncthreads();

    float acc[2][8][4];
#pragma unroll
    for (int mt = 0; mt < 2; mt++)
#pragma unroll
        for (int ns = 0; ns < 8; ns++)
#pragma unroll
            for (int i = 0; i < 4; i++) acc[mt][ns][i] = 0.f;

// fragment-packed KLOOP: per 16-K block: 4 ldmatrix + 8 coalesced LDG.128 + 48 HMMA
#define KLOOP(FRAG, NKB, KB0)                                                    \
    _Pragma("unroll 2")                                                          \
    for (int kbi = 0; kbi < (NKB); kbi++) {                                      \
        uint32_t ah0[4], ah1[4], al0[4], al1[4];                                 \
        uint32_t arow = (uint32_t)(((mrow + (lane & 15)) * KS + kbi * 16 +       \
                                    ((lane >> 4) << 3)) * 2);                    \
        ldm4(ah0, smb + A_HI + arow);                                            \
        ldm4(ah1, smb + A_HI + arow + 16 * KS * 2);                              \
        ldm4(al0, smb + A_LO + arow);                                            \
        ldm4(al1, smb + A_LO + arow + 16 * KS * 2);                              \
        const uint4* wf = (FRAG) + ((size_t)((KB0) + kbi) * 32 + (ncol >> 3)) * 32 + lane; \
        _Pragma("unroll")                                                        \
        for (int ns = 0; ns < 8; ns++) {                                         \
            uint4 f = __ldg(wf + ns * 32);                                       \
            mma16816(acc[0][ns], ah0, f.x, f.y);                                 \
            mma16816(acc[0][ns], ah0, f.z, f.w);                                 \
            mma16816(acc[0][ns], al0, f.x, f.y);                                 \
            mma16816(acc[1][ns], ah1, f.x, f.y);                                 \
            mma16816(acc[1][ns], ah1, f.z, f.w);                                 \
            mma16816(acc[1][ns], al1, f.x, f.y);                                 \
        }                                                                        \
    }

    // =================== layer 0: 4 K-chunks ===================
    for (int c = 0; c < 4; c++) {
        if (c < 3) {
            // gather level c -> A[64][256] hi/lo
            int s = tid >> 2, q = tid & 3;
            const float* lsrc = (c == 0) ? grid : (c == 1 ? g_l1 : g_l2);
            const float4* src = (const float4*)lsrc;
            const int* mo = (const int*)(sm + SM_METAO) + (c * 64 + s) * 4;
            const float* mw = (const float*)(sm + SM_METAW) + (c * 64 + s) * 4;
            int o0 = mo[0], o1 = mo[1], o2 = mo[2], o3 = mo[3];
            float w0v = mw[0], w1v = mw[1], w2v = mw[2], w3v = mw[3];
#pragma unroll
            for (int ch = 0; ch < 16; ch++) {
                int d4 = q * 16 + ch;
                float4 A = __ldg(&src[o0 + d4]);
                float4 B = __ldg(&src[o1 + d4]);
                float4 C = __ldg(&src[o2 + d4]);
                float4 D = __ldg(&src[o3 + d4]);
                float vx = w0v * A.x + w1v * B.x + w2v * C.x + w3v * D.x;
                float vy = w0v * A.y + w1v * B.y + w2v * C.y + w3v * D.y;
                float vz = w0v * A.z + w1v * B.z + w2v * C.z + w3v * D.z;
                float vw = w0v * A.w + w1v * B.w + w2v * C.w + w3v * D.w;
                int off = (s * KS + q * 64 + ch * 4) * 2;
                *(uint2*)(sm + A_HI + off) = make_uint2(pack_hi(vx, vy), pack_hi(vz, vw));
                *(uint2*)(sm + A_LO + off) = make_uint2(pack_lo(vx, vy), pack_lo(vz, vw));
            }
        } else if (tid < 64) {
            // PE + oracle + zero pad (64 k wide)
            int s = tid, n = n0 + s;
            float a[64];
            float c0v = coords[2 * n], c1v = coords[2 * n + 1];
            a[0] = c0v; a[1] = c1v;
            float pf = 3.14159265358979323846f;
#pragma unroll
            for (int f = 0; f < 10; f++) {
                float s0, q0, s1, q1;
                sincosf(c0v * pf, &s0, &q0);
                sincosf(c1v * pf, &s1, &q1);
                a[2 + 4 * f + 0] = s0; a[2 + 4 * f + 1] = s1;
                a[2 + 4 * f + 2] = q0; a[2 + 4 * f + 3] = q1;
                pf *= 2.0f;
            }
#pragma unroll
            for (int j = 0; j < 3; j++)
                a[42 + j] = oracle[((size_t)b * Nc + n) * 3 + j];
#pragma unroll
            for (int j = 45; j < 64; j++) a[j] = 0.f;
#pragma unroll
            for (int i = 0; i < 16; i++) {
                int off = (s * KS + i * 4) * 2;
                *(uint2*)(sm + A_HI + off) =
                    make_uint2(pack_hi(a[4 * i], a[4 * i + 1]), pack_hi(a[4 * i + 2], a[4 * i + 3]));
                *(uint2*)(sm + A_LO + off) =
                    make_uint2(pack_lo(a[4 * i], a[4 * i + 1]), pack_lo(a[4 * i + 2], a[4 * i + 3]));
            }
        }
        __syncthreads();
        if (c < 3) { KLOOP(g_w0f, 16, c * 16) }
        else       { KLOOP(g_w0f, 4, 48) }
        __syncthreads();
    }

    // =================== hidden layers ===================
    const float* gam = smf + (SM_GAMMA >> 2);
    const float* bet = smf + (SM_BETA >> 2);
    for (int L = 0; L < 3; L++) {
        const float* bias = smf + (SM_BIAS >> 2) + L * 256;
        // epilogue: gelu(FiLM) in place
#pragma unroll
        for (int mt = 0; mt < 2; mt++)
#pragma unroll
            for (int ns = 0; ns < 8; ns++) {
                int nn0 = ncol + ns * 8 + 2 * t, nn1 = nn0 + 1;
                float ga0 = gam[nn0], ga1 = gam[nn1];
                float be0 = bet[nn0], be1 = bet[nn1];
                float bi0 = bias[nn0], bi1 = bias[nn1];
                acc[mt][ns][0] = gelu_t((acc[mt][ns][0] + bi0) * ga0 + be0);
                acc[mt][ns][1] = gelu_t((acc[mt][ns][1] + bi1) * ga1 + be1);
                acc[mt][ns][2] = gelu_t((acc[mt][ns][2] + bi0) * ga0 + be0);
                acc[mt][ns][3] = gelu_t((acc[mt][ns][3] + bi1) * ga1 + be1);
            }
        __syncthreads();
#pragma unroll
        for (int mt = 0; mt < 2; mt++)
#pragma unroll
            for (int ns = 0; ns < 8; ns++) {
                int nn0 = ncol + ns * 8 + 2 * t;
                int r0 = mrow + mt * 16 + g, r1 = r0 + 8;
                *(uint32_t*)(sm + A_HI + (r0 * KS + nn0) * 2) = pack_hi(acc[mt][ns][0], acc[mt][ns][1]);
                *(uint32_t*)(sm + A_LO + (r0 * KS + nn0) * 2) = pack_lo(acc[mt][ns][0], acc[mt][ns][1]);
                *(uint32_t*)(sm + A_HI + (r1 * KS + nn0) * 2) = pack_hi(acc[mt][ns][2], acc[mt][ns][3]);
                *(uint32_t*)(sm + A_LO + (r1 * KS + nn0) * 2) = pack_lo(acc[mt][ns][2], acc[mt][ns][3]);
#pragma unroll
                for (int i = 0; i < 4; i++) acc[mt][ns][i] = 0.f;
            }
        __syncthreads();
        KLOOP(g_hwf + (size_t)L * 16384, 16, 0)
    }

    // =================== output layer ===================
    {
        const float* bias = smf + (SM_BIAS >> 2) + 3 * 256;
        const float* oww = smf + (SM_OW >> 2);
        float p[4][3];
#pragma unroll
        for (int i = 0; i < 4; i++) p[i][0] = p[i][1] = p[i][2] = 0.f;
#pragma unroll
        for (int mt = 0; mt < 2; mt++)
#pragma unroll
            for (int ns = 0; ns < 8; ns++) {
                int nn0 = ncol + ns * 8 + 2 * t, nn1 = nn0 + 1;
                float ga0 = gam[nn0], ga1 = gam[nn1];
                float be0 = bet[nn0], be1 = bet[nn1];
                float bi0 = bias[nn0], bi1 = bias[nn1];
                float v0 = gelu_t((acc[mt][ns][0] + bi0) * ga0 + be0);
                float v1 = gelu_t((acc[mt][ns][1] + bi1) * ga1 + be1);
                float v2 = gelu_t((acc[mt][ns][2] + bi0) * ga0 + be0);
                float v3 = gelu_t((acc[mt][ns][3] + bi1) * ga1 + be1);
#pragma unroll
                for (int o = 0; o < 3; o++) {
                    float w0o = oww[nn0 * 3 + o], w1o = oww[nn1 * 3 + o];
                    p[mt * 2 + 0][o] += v0 * w0o + v1 * w1o;
                    p[mt * 2 + 1][o] += v2 * w0o + v3 * w1o;
                }
            }
#pragma unroll
        for (int i = 0; i < 4; i++)
#pragma unroll
            for (int o = 0; o < 3; o++) {
                p[i][o] += __shfl_xor_sync(0xffffffffu, p[i][o], 1);
                p[i][o] += __shfl_xor_sync(0xffffffffu, p[i][o], 2);
            }
        if (t == 0) {
#pragma unroll
            for (int mt = 0; mt < 2; mt++) {
                int r0 = mrow + mt * 16 + g, r1 = r0 + 8;
#pragma unroll
                for (int o = 0; o < 3; o++) {
                    atomicAdd(smf + (SM_PSUM >> 2) + r0 * 3 + o, p[mt * 2 + 0][o]);
                    atomicAdd(smf + (SM_PSUM >> 2) + r1 * 3 + o, p[mt * 2 + 1][o]);
                }
            }
        }
    }
    __syncthreads();
    if (tid < 64) {
        const float* obv = smf + (SM_OW >> 2) + 768;
#pragma unroll
        for (int o = 0; o < 3; o++)
            out[((size_t)b * Nc + n0 + tid) * 3 + o] =
                tanhf(smf[(SM_PSUM >> 2) + tid * 3 + o] + obv[o]);
    }
}

// ---------------- launch ----------------
extern "C" void kernel_launch(void* const* d_in, const int* in_sizes, int n_in,
                              void* d_out, int out_size) {
    const float* grid   = (const float*)d_in[0];
    const float* cv     = (const float*)d_in[1];
    const float* coords = (const float*)d_in[2];
    const float* oracle = (const float*)d_in[3];
    const float* w0     = (const float*)d_in[4];
    const float* b0     = (const float*)d_in[5];
    const float* hw     = (const float*)d_in[6];
    const float* hb     = (const float*)d_in[7];
    const float* cw     = (const float*)d_in[8];
    const float* cb     = (const float*)d_in[9];
    const float* ow     = (const float*)d_in[10];
    const float* ob     = (const float*)d_in[11];
    float* out = (float*)d_out;

    cudaFuncSetAttribute(fused_kernel, cudaFuncAttributeMaxDynamicSharedMemorySize, SM_TOTAL);

    resize2d_l1_kernel<<<(Bc * 64 * 64 * 64 + 255) / 256, 256>>>(grid);
    resize2d_l2_kernel<<<(Bc * 32 * 32 * 64 + 255) / 256, 256>>>(grid);
    film_kernel<<<Bc, 512>>>(cv, cw, cb);
    prep_w0f<<<(52 * 32 * 32 + 255) / 256, 256>>>(w0);
    prep_hwf<<<(3 * 16 * 32 * 32 + 255) / 256, 256>>>(hw);
    fused_kernel<<<Bc * Nc / 64, THREADS, SM_TOTAL>>>(grid, coords, oracle,
                                                      b0, hb, ow, ob, out);
}

// round 14
// speedup vs baseline: 1.4080x; 1.2596x over previous
#include <cuda_runtime.h>
#include <cuda_fp16.h>
#include <math.h>
#include <stdint.h>

#define Bc    8
#define Hc    128
#define Wc    128
#define Dc    256
#define Nc    8192
#define THREADS 256

// SMEM byte offsets
#define KS       264            // fp16 stride per activation row (528B = 33*16B)
#define A_HI     0              // 64*264*2 = 33792 (single plane)
#define SM_METAO 33792          // 3*64*4 int
#define SM_METAW 36864          // 3*64*4 float
#define SM_GAMMA 39936          // 256 f32
#define SM_BETA  40960
#define SM_BIAS  41984          // 4*256 f32
#define SM_OW    46080          // 771 f32
#define SM_PSUM  49168          // 64*3 f32
#define SM_TOTAL 49984

// ---------------- device scratch ----------------
__device__ float g_l1[Bc * 64 * 64 * Dc];   // level1 (33 MB)
__device__ float g_l2[Bc * 32 * 32 * Dc];   // level2 (8 MB)
__device__ float g_film[Bc * 512];
// fragment-packed fp16 weights: [kb][n8 group][lane] -> {hi01, hi89, lo01, lo89}
__device__ __align__(16) uint4 g_w0f[52 * 32 * 32];      // layer0, K padded to 832
__device__ __align__(16) uint4 g_hwf[3 * 16 * 32 * 32];  // hidden layers

// ---------------- helpers ----------------
__device__ __forceinline__ uint32_t smem_u32(const void* p) {
    uint32_t a;
    asm("{ .reg .u64 t; cvta.to.shared.u64 t, %1; cvt.u32.u64 %0, t; }" : "=r"(a) : "l"(p));
    return a;
}
__device__ __forceinline__ void ldm4(uint32_t* r, uint32_t addr) {
    asm volatile("ldmatrix.sync.aligned.m8n8.x4.shared.b16 {%0,%1,%2,%3}, [%4];"
        : "=r"(r[0]), "=r"(r[1]), "=r"(r[2]), "=r"(r[3]) : "r"(addr));
}
__device__ __forceinline__ void mma16816(float* c, const uint32_t* a, uint32_t b0, uint32_t b1) {
    asm volatile("mma.sync.aligned.m16n8k16.row.col.f32.f16.f16.f32 "
        "{%0,%1,%2,%3}, {%4,%5,%6,%7}, {%8,%9}, {%0,%1,%2,%3};"
        : "+f"(c[0]), "+f"(c[1]), "+f"(c[2]), "+f"(c[3])
        : "r"(a[0]), "r"(a[1]), "r"(a[2]), "r"(a[3]), "r"(b0), "r"(b1));
}
__device__ __forceinline__ uint32_t pack_h(float x, float y) {
    __half2 v = __floats2half2_rn(x, y);
    return *(uint32_t*)&v;
}
__device__ __forceinline__ uint32_t pack_hlo(float x, float y) {
    float hx = __half2float(__float2half_rn(x));
    float hy = __half2float(__float2half_rn(y));
    __half2 v = __floats2half2_rn(x - hx, y - hy);
    return *(uint32_t*)&v;
}
__device__ __forceinline__ float gelu_t(float x) {
    float x3 = x * x * x;
    float t = tanhf(0.7978845608028654f * (x + 0.044715f * x3));
    return 0.5f * x * (1.0f + t);
}

// ---------------- direct 2D antialiased triangle resize ----------------
template <int INV, int OUTW>
__device__ __forceinline__ void resize2d_body(const float* __restrict__ in,
                                              float* __restrict__ out) {
    const int NT = 2 * INV;
    int idx = blockIdx.x * blockDim.x + threadIdx.x;
    if (idx >= Bc * OUTW * OUTW * 64) return;
    int d4 = idx & 63;
    int t2 = idx >> 6;
    int xo = t2 % OUTW; t2 /= OUTW;
    int yo = t2 % OUTW;
    int b = t2 / OUTW;

    int jy0 = INV * yo - (INV / 2), jx0 = INV * xo - (INV / 2);
    float sfy = (yo + 0.5f) * INV - 0.5f, sfx = (xo + 0.5f) * INV - 0.5f;
    float wy[NT], wx[NT], sy = 0.f, sx = 0.f;
#pragma unroll
    for (int i = 0; i < NT; i++) {
        int jy = jy0 + i;
        float w = 1.0f - fabsf((float)jy - sfy) * (1.0f / INV);
        w = (jy >= 0 && jy < Hc) ? fmaxf(w, 0.f) : 0.f;
        wy[i] = w; sy += w;
        int jx = jx0 + i;
        float v = 1.0f - fabsf((float)jx - sfx) * (1.0f / INV);
        v = (jx >= 0 && jx < Wc) ? fmaxf(v, 0.f) : 0.f;
        wx[i] = v; sx += v;
    }
    float norm = 1.0f / (sy * sx);

    const float4* ip = (const float4*)in + (size_t)b * Hc * Wc * 64 + d4;
    float4 acc = make_float4(0.f, 0.f, 0.f, 0.f);
#pragma unroll
    for (int iy = 0; iy < NT; iy++) {
        if (wy[iy] <= 0.f) continue;
        const float4* rp = ip + (size_t)(jy0 + iy) * Wc * 64;
#pragma unroll
        for (int ix = 0; ix < NT; ix++) {
            if (wx[ix] <= 0.f) continue;
            float4 v = __ldg(rp + (jx0 + ix) * 64);
            float w = wy[iy] * wx[ix];
            acc.x += w * v.x; acc.y += w * v.y; acc.z += w * v.z; acc.w += w * v.w;
        }
    }
    ((float4*)out)[((size_t)(b * OUTW + yo) * OUTW + xo) * 64 + d4] =
        make_float4(acc.x * norm, acc.y * norm, acc.z * norm, acc.w * norm);
}

__global__ void resize2d_l1_kernel(const float* __restrict__ in) {
    resize2d_body<2, 64>(in, g_l1);
}
__global__ void resize2d_l2_kernel(const float* __restrict__ in) {
    resize2d_body<4, 32>(in, g_l2);
}

// ---------------- FiLM ----------------
__global__ void film_kernel(const float* __restrict__ cv, const float* __restrict__ cw,
                            const float* __restrict__ cb) {
    int b = blockIdx.x, j = threadIdx.x;
    float acc = cb[j];
    for (int k = 0; k < Dc; k++) acc = fmaf(cv[b * Dc + k], cw[k * 512 + j], acc);
    g_film[b * 512 + j] = acc;
}

// ---------------- weight prep: fragment packing + fp16 hi/lo split ----------------
__device__ __forceinline__ float w0val(const float* __restrict__ w0, int kp, int n) {
    if (kp >= 813) return 0.f;
    int orig;
    if (kp < 768) orig = 42 + (kp >> 8) * 256 + (kp & 255);
    else if (kp < 810) orig = kp - 768;
    else orig = kp;
    return w0[orig * 256 + n];
}

__global__ void prep_w0f(const float* __restrict__ w0) {
    int idx = blockIdx.x * blockDim.x + threadIdx.x;
    if (idx >= 52 * 32 * 32) return;
    int lane = idx & 31, nq = (idx >> 5) & 31, kb = idx >> 10;
    int g = lane >> 2, t = lane & 3;
    int row = nq * 8 + g;
    int k0 = kb * 16 + 2 * t;
    float v0 = w0val(w0, k0, row),     v1 = w0val(w0, k0 + 1, row);
    float v2 = w0val(w0, k0 + 8, row), v3 = w0val(w0, k0 + 9, row);
    g_w0f[idx] = make_uint4(pack_h(v0, v1), pack_h(v2, v3),
                            pack_hlo(v0, v1), pack_hlo(v2, v3));
}
__global__ void prep_hwf(const float* __restrict__ hw) {
    int idx = blockIdx.x * blockDim.x + threadIdx.x;
    if (idx >= 3 * 16 * 32 * 32) return;
    int lane = idx & 31, nq = (idx >> 5) & 31, kb = (idx >> 10) & 15, L = idx >> 14;
    int g = lane >> 2, t = lane & 3;
    int row = nq * 8 + g;
    int k0 = kb * 16 + 2 * t;
    const float* W = hw + (size_t)L * 65536;
    float v0 = W[k0 * 256 + row],       v1 = W[(k0 + 1) * 256 + row];
    float v2 = W[(k0 + 8) * 256 + row], v3 = W[(k0 + 9) * 256 + row];
    g_hwf[idx] = make_uint4(pack_h(v0, v1), pack_h(v2, v3),
                            pack_hlo(v0, v1), pack_hlo(v2, v3));
}

// ---------------- fused kernel ----------------
__global__ void __launch_bounds__(THREADS, 2)
fused_kernel(const float* __restrict__ grid,
             const float* __restrict__ coords,
             const float* __restrict__ oracle,
             const float* __restrict__ b0, const float* __restrict__ hb,
             const float* __restrict__ ow, const float* __restrict__ ob,
             float* __restrict__ out) {
    extern __shared__ char sm[];
    uint32_t smb = smem_u32(sm);
    float* smf = (float*)sm;
    int tid = threadIdx.x;
    int lane = tid & 31;
    int w = tid >> 5;
    int blk = blockIdx.x;
    int b = blk >> 7;               // 128 tiles of 64 per batch
    int n0 = (blk & 127) * 64;
    int mrow = (w & 1) * 32;        // warp M offset
    int ncol = (w >> 1) * 64;       // warp N offset
    int g = lane >> 2, t = lane & 3;

    // film / biases / out weights / psum init
    smf[(SM_GAMMA >> 2) + tid] = g_film[b * 512 + tid] + 1.0f;
    smf[(SM_BETA >> 2) + tid] = g_film[b * 512 + 256 + tid];
    smf[(SM_BIAS >> 2) + tid] = b0[tid];
#pragma unroll
    for (int l = 0; l < 3; l++)
        smf[(SM_BIAS >> 2) + 256 + l * 256 + tid] = hb[l * 256 + tid];
    for (int i = tid; i < 771; i += THREADS)
        smf[(SM_OW >> 2) + i] = (i < 768) ? ow[i] : ob[i - 768];
    if (tid < 192) smf[(SM_PSUM >> 2) + tid] = 0.f;

    // bilinear metadata: 3 levels x 64 samples
    if (tid < 192) {
        int lvl = tid >> 6, s = tid & 63;
        int n = n0 + s;
        int Hl = Hc >> lvl, Wl = Wc >> lvl;
        float c0 = coords[2 * n], c1 = coords[2 * n + 1];
        float y = (c0 + 1.0f) * 0.5f * (Hl - 1);
        float x = (c1 + 1.0f) * 0.5f * (Wl - 1);
        float y0f = fminf(fmaxf(floorf(y), 0.f), (float)(Hl - 1));
        float x0f = fminf(fmaxf(floorf(x), 0.f), (float)(Wl - 1));
        int y0 = (int)y0f, x0 = (int)x0f;
        int y1 = min(y0 + 1, Hl - 1), x1 = min(x0 + 1, Wl - 1);
        float wy = y - y0f, wx = x - x0f;
        int base = b * Hl * Wl;
        int* mo = (int*)(sm + SM_METAO) + tid * 4;
        float* mw = (float*)(sm + SM_METAW) + tid * 4;
        mo[0] = (base + y0 * Wl + x0) * 64;
        mo[1] = (base + y0 * Wl + x1) * 64;
        mo[2] = (base + y1 * Wl + x0) * 64;
        mo[3] = (base + y1 * Wl + x1) * 64;
        mw[0] = (1.f - wy) * (1.f - wx);
        mw[1] = (1.f - wy) * wx;
        mw[2] = wy * (1.f - wx);
        mw[3] = wy * wx;
    }
    __syncthreads();

    float acc[2][8][4];
#pragma unroll
    for (int mt = 0; mt < 2; mt++)
#pragma unroll
        for (int ns = 0; ns < 8; ns++)
#pragma unroll
            for (int i = 0; i < 4; i++) acc[mt][ns][i] = 0.f;

// fp16 2-term KLOOP: per 16-K block: 2 ldmatrix + 8 coalesced LDG.128 + 32 HMMA
#define KLOOP(FRAG, NKB, KB0)                                                    \
    _Pragma("unroll 2")                                                          \
    for (int kbi = 0; kbi < (NKB); kbi++) {                                      \
        uint32_t ah0[4], ah1[4];                                                 \
        uint32_t arow = (uint32_t)(((mrow + (lane & 15)) * KS + kbi * 16 +       \
                                    ((lane >> 4) << 3)) * 2);                    \
        ldm4(ah0, smb + A_HI + arow);                                            \
        ldm4(ah1, smb + A_HI + arow + 16 * KS * 2);                              \
        const uint4* wf = (FRAG) + ((size_t)((KB0) + kbi) * 32 + (ncol >> 3)) * 32 + lane; \
        _Pragma("unroll")                                                        \
        for (int ns = 0; ns < 8; ns++) {                                         \
            uint4 f = __ldg(wf + ns * 32);                                       \
            mma16816(acc[0][ns], ah0, f.x, f.y);                                 \
            mma16816(acc[0][ns], ah0, f.z, f.w);                                 \
            mma16816(acc[1][ns], ah1, f.x, f.y);                                 \
            mma16816(acc[1][ns], ah1, f.z, f.w);                                 \
        }                                                                        \
    }

    // =================== layer 0: 4 K-chunks ===================
    for (int c = 0; c < 4; c++) {
        if (c < 3) {
            // gather level c -> A[64][256] fp16
            int s = tid >> 2, q = tid & 3;
            const float* lsrc = (c == 0) ? grid : (c == 1 ? g_l1 : g_l2);
            const float4* src = (const float4*)lsrc;
            const int* mo = (const int*)(sm + SM_METAO) + (c * 64 + s) * 4;
            const float* mw = (const float*)(sm + SM_METAW) + (c * 64 + s) * 4;
            int o0 = mo[0], o1 = mo[1], o2 = mo[2], o3 = mo[3];
            float w0v = mw[0], w1v = mw[1], w2v = mw[2], w3v = mw[3];
#pragma unroll
            for (int ch = 0; ch < 16; ch++) {
                int d4 = q * 16 + ch;
                float4 A = __ldg(&src[o0 + d4]);
                float4 B = __ldg(&src[o1 + d4]);
                float4 C = __ldg(&src[o2 + d4]);
                float4 D = __ldg(&src[o3 + d4]);
                float vx = w0v * A.x + w1v * B.x + w2v * C.x + w3v * D.x;
                float vy = w0v * A.y + w1v * B.y + w2v * C.y + w3v * D.y;
                float vz = w0v * A.z + w1v * B.z + w2v * C.z + w3v * D.z;
                float vw = w0v * A.w + w1v * B.w + w2v * C.w + w3v * D.w;
                int off = (s * KS + q * 64 + ch * 4) * 2;
                *(uint2*)(sm + A_HI + off) = make_uint2(pack_h(vx, vy), pack_h(vz, vw));
            }
        } else if (tid < 64) {
            // PE + oracle + zero pad (64 k wide)
            int s = tid, n = n0 + s;
            float a[64];
            float c0v = coords[2 * n], c1v = coords[2 * n + 1];
            a[0] = c0v; a[1] = c1v;
            float pf = 3.14159265358979323846f;
#pragma unroll
            for (int f = 0; f < 10; f++) {
                float s0, q0, s1, q1;
                sincosf(c0v * pf, &s0, &q0);
                sincosf(c1v * pf, &s1, &q1);
                a[2 + 4 * f + 0] = s0; a[2 + 4 * f + 1] = s1;
                a[2 + 4 * f + 2] = q0; a[2 + 4 * f + 3] = q1;
                pf *= 2.0f;
            }
#pragma unroll
            for (int j = 0; j < 3; j++)
                a[42 + j] = oracle[((size_t)b * Nc + n) * 3 + j];
#pragma unroll
            for (int j = 45; j < 64; j++) a[j] = 0.f;
#pragma unroll
            for (int i = 0; i < 16; i++) {
                int off = (s * KS + i * 4) * 2;
                *(uint2*)(sm + A_HI + off) =
                    make_uint2(pack_h(a[4 * i], a[4 * i + 1]), pack_h(a[4 * i + 2], a[4 * i + 3]));
            }
        }
        __syncthreads();
        if (c < 3) { KLOOP(g_w0f, 16, c * 16) }
        else       { KLOOP(g_w0f, 4, 48) }
        __syncthreads();
    }

    // =================== hidden layers ===================
    const float* gam = smf + (SM_GAMMA >> 2);
    const float* bet = smf + (SM_BETA >> 2);
    for (int L = 0; L < 3; L++) {
        const float* bias = smf + (SM_BIAS >> 2) + L * 256;
        // epilogue: gelu(FiLM) in place
#pragma unroll
        for (int mt = 0; mt < 2; mt++)
#pragma unroll
            for (int ns = 0; ns < 8; ns++) {
                int nn0 = ncol + ns * 8 + 2 * t, nn1 = nn0 + 1;
                float ga0 = gam[nn0], ga1 = gam[nn1];
                float be0 = bet[nn0], be1 = bet[nn1];
                float bi0 = bias[nn0], bi1 = bias[nn1];
                acc[mt][ns][0] = gelu_t((acc[mt][ns][0] + bi0) * ga0 + be0);
                acc[mt][ns][1] = gelu_t((acc[mt][ns][1] + bi1) * ga1 + be1);
                acc[mt][ns][2] = gelu_t((acc[mt][ns][2] + bi0) * ga0 + be0);
                acc[mt][ns][3] = gelu_t((acc[mt][ns][3] + bi1) * ga1 + be1);
            }
        __syncthreads();
#pragma unroll
        for (int mt = 0; mt < 2; mt++)
#pragma unroll
            for (int ns = 0; ns < 8; ns++) {
                int nn0 = ncol + ns * 8 + 2 * t;
                int r0 = mrow + mt * 16 + g, r1 = r0 + 8;
                *(uint32_t*)(sm + A_HI + (r0 * KS + nn0) * 2) = pack_h(acc[mt][ns][0], acc[mt][ns][1]);
                *(uint32_t*)(sm + A_HI + (r1 * KS + nn0) * 2) = pack_h(acc[mt][ns][2], acc[mt][ns][3]);
#pragma unroll
                for (int i = 0; i < 4; i++) acc[mt][ns][i] = 0.f;
            }
        __syncthreads();
        KLOOP(g_hwf + (size_t)L * 16384, 16, 0)
    }

    // =================== output layer ===================
    {
        const float* bias = smf + (SM_BIAS >> 2) + 3 * 256;
        const float* oww = smf + (SM_OW >> 2);
        float p[4][3];
#pragma unroll
        for (int i = 0; i < 4; i++) p[i][0] = p[i][1] = p[i][2] = 0.f;
#pragma unroll
        for (int mt = 0; mt < 2; mt++)
#pragma unroll
            for (int ns = 0; ns < 8; ns++) {
                int nn0 = ncol + ns * 8 + 2 * t, nn1 = nn0 + 1;
                float ga0 = gam[nn0], ga1 = gam[nn1];
                float be0 = bet[nn0], be1 = bet[nn1];
                float bi0 = bias[nn0], bi1 = bias[nn1];
                float v0 = gelu_t((acc[mt][ns][0] + bi0) * ga0 + be0);
                float v1 = gelu_t((acc[mt][ns][1] + bi1) * ga1 + be1);
                float v2 = gelu_t((acc[mt][ns][2] + bi0) * ga0 + be0);
                float v3 = gelu_t((acc[mt][ns][3] + bi1) * ga1 + be1);
#pragma unroll
                for (int o = 0; o < 3; o++) {
                    float w0o = oww[nn0 * 3 + o], w1o = oww[nn1 * 3 + o];
                    p[mt * 2 + 0][o] += v0 * w0o + v1 * w1o;
                    p[mt * 2 + 1][o] += v2 * w0o + v3 * w1o;
                }
            }
#pragma unroll
        for (int i = 0; i < 4; i++)
#pragma unroll
            for (int o = 0; o < 3; o++) {
                p[i][o] += __shfl_xor_sync(0xffffffffu, p[i][o], 1);
                p[i][o] += __shfl_xor_sync(0xffffffffu, p[i][o], 2);
            }
        if (t == 0) {
#pragma unroll
            for (int mt = 0; mt < 2; mt++) {
                int r0 = mrow + mt * 16 + g, r1 = r0 + 8;
#pragma unroll
                for (int o = 0; o < 3; o++) {
                    atomicAdd(smf + (SM_PSUM >> 2) + r0 * 3 + o, p[mt * 2 + 0][o]);
                    atomicAdd(smf + (SM_PSUM >> 2) + r1 * 3 + o, p[mt * 2 + 1][o]);
                }
            }
        }
    }
    __syncthreads();
    if (tid < 64) {
        const float* obv = smf + (SM_OW >> 2) + 768;
#pragma unroll
        for (int o = 0; o < 3; o++)
            out[((size_t)b * Nc + n0 + tid) * 3 + o] =
                tanhf(smf[(SM_PSUM >> 2) + tid * 3 + o] + obv[o]);
    }
}

// ---------------- launch ----------------
extern "C" void kernel_launch(void* const* d_in, const int* in_sizes, int n_in,
                              void* d_out, int out_size) {
    const float* grid   = (const float*)d_in[0];
    const float* cv     = (const float*)d_in[1];
    const float* coords = (const float*)d_in[2];
    const float* oracle = (const float*)d_in[3];
    const float* w0     = (const float*)d_in[4];
    const float* b0     = (const float*)d_in[5];
    const float* hw     = (const float*)d_in[6];
    const float* hb     = (const float*)d_in[7];
    const float* cw     = (const float*)d_in[8];
    const float* cb     = (const float*)d_in[9];
    const float* ow     = (const float*)d_in[10];
    const float* ob     = (const float*)d_in[11];
    float* out = (float*)d_out;

    cudaFuncSetAttribute(fused_kernel, cudaFuncAttributeMaxDynamicSharedMemorySize, SM_TOTAL);

    resize2d_l1_kernel<<<(Bc * 64 * 64 * 64 + 255) / 256, 256>>>(grid);
    resize2d_l2_kernel<<<(Bc * 32 * 32 * 64 + 255) / 256, 256>>>(grid);
    film_kernel<<<Bc, 512>>>(cv, cw, cb);
    prep_w0f<<<(52 * 32 * 32 + 255) / 256, 256>>>(w0);
    prep_hwf<<<(3 * 16 * 32 * 32 + 255) / 256, 256>>>(hw);
    fused_kernel<<<Bc * Nc / 64, THREADS, SM_TOTAL>>>(grid, coords, oracle,
                                                      b0, hb, ow, ob, out);
}

// round 15
// speedup vs baseline: 1.6748x; 1.1895x over previous
#include <cuda_runtime.h>
#include <cuda_fp16.h>
#include <math.h>
#include <stdint.h>

#define Bc    8
#define Hc    128
#define Wc    128
#define Dc    256
#define Nc    8192
#define THREADS 256

// SMEM byte offsets
#define KS       264            // fp16 stride per activation row (528B = 33*16B)
#define A_HI     0              // 64*264*2 = 33792 (single plane)
#define SM_METAO 33792          // 3*64*4 int
#define SM_METAW 36864          // 3*64*4 float
#define SM_GAMMA 39936          // 256 f32
#define SM_BETA  40960
#define SM_BIAS  41984          // 4*256 f32
#define SM_OW    46080          // 771 f32
#define SM_PSUM  49168          // 64*3 f32
#define SM_TOTAL 49984

// ---------------- device scratch ----------------
__device__ float g_l1[Bc * 64 * 64 * Dc];   // level1 (33 MB)
__device__ float g_l2[Bc * 32 * 32 * Dc];   // level2 (8 MB)
__device__ float g_film[Bc * 512];
// fragment-packed fp16 weights (single plane): [kb][n8 group][lane] -> {b01, b89}
__device__ __align__(16) uint2 g_w0f[52 * 32 * 32];      // layer0, K padded to 832
__device__ __align__(16) uint2 g_hwf[3 * 16 * 32 * 32];  // hidden layers

// ---------------- helpers ----------------
__device__ __forceinline__ uint32_t smem_u32(const void* p) {
    uint32_t a;
    asm("{ .reg .u64 t; cvta.to.shared.u64 t, %1; cvt.u32.u64 %0, t; }" : "=r"(a) : "l"(p));
    return a;
}
__device__ __forceinline__ void ldm4(uint32_t* r, uint32_t addr) {
    asm volatile("ldmatrix.sync.aligned.m8n8.x4.shared.b16 {%0,%1,%2,%3}, [%4];"
        : "=r"(r[0]), "=r"(r[1]), "=r"(r[2]), "=r"(r[3]) : "r"(addr));
}
__device__ __forceinline__ void mma16816(float* c, const uint32_t* a, uint32_t b0, uint32_t b1) {
    asm volatile("mma.sync.aligned.m16n8k16.row.col.f32.f16.f16.f32 "
        "{%0,%1,%2,%3}, {%4,%5,%6,%7}, {%8,%9}, {%0,%1,%2,%3};"
        : "+f"(c[0]), "+f"(c[1]), "+f"(c[2]), "+f"(c[3])
        : "r"(a[0]), "r"(a[1]), "r"(a[2]), "r"(a[3]), "r"(b0), "r"(b1));
}
__device__ __forceinline__ uint32_t pack_h(float x, float y) {
    __half2 v = __floats2half2_rn(x, y);
    return *(uint32_t*)&v;
}
__device__ __forceinline__ float gelu_t(float x) {
    float x3 = x * x * x;
    float t = tanhf(0.7978845608028654f * (x + 0.044715f * x3));
    return 0.5f * x * (1.0f + t);
}

// ---------------- direct 2D antialiased triangle resize ----------------
template <int INV, int OUTW>
__device__ __forceinline__ void resize2d_body(const float* __restrict__ in,
                                              float* __restrict__ out) {
    const int NT = 2 * INV;
    int idx = blockIdx.x * blockDim.x + threadIdx.x;
    if (idx >= Bc * OUTW * OUTW * 64) return;
    int d4 = idx & 63;
    int t2 = idx >> 6;
    int xo = t2 % OUTW; t2 /= OUTW;
    int yo = t2 % OUTW;
    int b = t2 / OUTW;

    int jy0 = INV * yo - (INV / 2), jx0 = INV * xo - (INV / 2);
    float sfy = (yo + 0.5f) * INV - 0.5f, sfx = (xo + 0.5f) * INV - 0.5f;
    float wy[NT], wx[NT], sy = 0.f, sx = 0.f;
#pragma unroll
    for (int i = 0; i < NT; i++) {
        int jy = jy0 + i;
        float w = 1.0f - fabsf((float)jy - sfy) * (1.0f / INV);
        w = (jy >= 0 && jy < Hc) ? fmaxf(w, 0.f) : 0.f;
        wy[i] = w; sy += w;
        int jx = jx0 + i;
        float v = 1.0f - fabsf((float)jx - sfx) * (1.0f / INV);
        v = (jx >= 0 && jx < Wc) ? fmaxf(v, 0.f) : 0.f;
        wx[i] = v; sx += v;
    }
    float norm = 1.0f / (sy * sx);

    const float4* ip = (const float4*)in + (size_t)b * Hc * Wc * 64 + d4;
    float4 acc = make_float4(0.f, 0.f, 0.f, 0.f);
#pragma unroll
    for (int iy = 0; iy < NT; iy++) {
        if (wy[iy] <= 0.f) continue;
        const float4* rp = ip + (size_t)(jy0 + iy) * Wc * 64;
#pragma unroll
        for (int ix = 0; ix < NT; ix++) {
            if (wx[ix] <= 0.f) continue;
            float4 v = __ldg(rp + (jx0 + ix) * 64);
            float w = wy[iy] * wx[ix];
            acc.x += w * v.x; acc.y += w * v.y; acc.z += w * v.z; acc.w += w * v.w;
        }
    }
    ((float4*)out)[((size_t)(b * OUTW + yo) * OUTW + xo) * 64 + d4] =
        make_float4(acc.x * norm, acc.y * norm, acc.z * norm, acc.w * norm);
}

__global__ void resize2d_l1_kernel(const float* __restrict__ in) {
    resize2d_body<2, 64>(in, g_l1);
}
__global__ void resize2d_l2_kernel(const float* __restrict__ in) {
    resize2d_body<4, 32>(in, g_l2);
}

// ---------------- FiLM ----------------
__global__ void film_kernel(const float* __restrict__ cv, const float* __restrict__ cw,
                            const float* __restrict__ cb) {
    int b = blockIdx.x, j = threadIdx.x;
    float acc = cb[j];
    for (int k = 0; k < Dc; k++) acc = fmaf(cv[b * Dc + k], cw[k * 512 + j], acc);
    g_film[b * 512 + j] = acc;
}

// ---------------- weight prep: fragment packing (single fp16 plane) ----------------
__device__ __forceinline__ float w0val(const float* __restrict__ w0, int kp, int n) {
    if (kp >= 813) return 0.f;
    int orig;
    if (kp < 768) orig = 42 + (kp >> 8) * 256 + (kp & 255);
    else if (kp < 810) orig = kp - 768;
    else orig = kp;
    return w0[orig * 256 + n];
}

__global__ void prep_w0f(const float* __restrict__ w0) {
    int idx = blockIdx.x * blockDim.x + threadIdx.x;
    if (idx >= 52 * 32 * 32) return;
    int lane = idx & 31, nq = (idx >> 5) & 31, kb = idx >> 10;
    int g = lane >> 2, t = lane & 3;
    int row = nq * 8 + g;
    int k0 = kb * 16 + 2 * t;
    float v0 = w0val(w0, k0, row),     v1 = w0val(w0, k0 + 1, row);
    float v2 = w0val(w0, k0 + 8, row), v3 = w0val(w0, k0 + 9, row);
    g_w0f[idx] = make_uint2(pack_h(v0, v1), pack_h(v2, v3));
}
__global__ void prep_hwf(const float* __restrict__ hw) {
    int idx = blockIdx.x * blockDim.x + threadIdx.x;
    if (idx >= 3 * 16 * 32 * 32) return;
    int lane = idx & 31, nq = (idx >> 5) & 31, kb = (idx >> 10) & 15, L = idx >> 14;
    int g = lane >> 2, t = lane & 3;
    int row = nq * 8 + g;
    int k0 = kb * 16 + 2 * t;
    const float* W = hw + (size_t)L * 65536;
    float v0 = W[k0 * 256 + row],       v1 = W[(k0 + 1) * 256 + row];
    float v2 = W[(k0 + 8) * 256 + row], v3 = W[(k0 + 9) * 256 + row];
    g_hwf[idx] = make_uint2(pack_h(v0, v1), pack_h(v2, v3));
}

// ---------------- fused kernel ----------------
__global__ void __launch_bounds__(THREADS, 2)
fused_kernel(const float* __restrict__ grid,
             const float* __restrict__ coords,
             const float* __restrict__ oracle,
             const float* __restrict__ b0, const float* __restrict__ hb,
             const float* __restrict__ ow, const float* __restrict__ ob,
             float* __restrict__ out) {
    extern __shared__ char sm[];
    uint32_t smb = smem_u32(sm);
    float* smf = (float*)sm;
    int tid = threadIdx.x;
    int lane = tid & 31;
    int w = tid >> 5;
    int blk = blockIdx.x;
    int b = blk >> 7;               // 128 tiles of 64 per batch
    int n0 = (blk & 127) * 64;
    int mrow = (w & 1) * 32;        // warp M offset
    int ncol = (w >> 1) * 64;       // warp N offset
    int g = lane >> 2, t = lane & 3;

    // film / biases / out weights / psum init
    smf[(SM_GAMMA >> 2) + tid] = g_film[b * 512 + tid] + 1.0f;
    smf[(SM_BETA >> 2) + tid] = g_film[b * 512 + 256 + tid];
    smf[(SM_BIAS >> 2) + tid] = b0[tid];
#pragma unroll
    for (int l = 0; l < 3; l++)
        smf[(SM_BIAS >> 2) + 256 + l * 256 + tid] = hb[l * 256 + tid];
    for (int i = tid; i < 771; i += THREADS)
        smf[(SM_OW >> 2) + i] = (i < 768) ? ow[i] : ob[i - 768];
    if (tid < 192) smf[(SM_PSUM >> 2) + tid] = 0.f;

    // bilinear metadata: 3 levels x 64 samples
    if (tid < 192) {
        int lvl = tid >> 6, s = tid & 63;
        int n = n0 + s;
        int Hl = Hc >> lvl, Wl = Wc >> lvl;
        float c0 = coords[2 * n], c1 = coords[2 * n + 1];
        float y = (c0 + 1.0f) * 0.5f * (Hl - 1);
        float x = (c1 + 1.0f) * 0.5f * (Wl - 1);
        float y0f = fminf(fmaxf(floorf(y), 0.f), (float)(Hl - 1));
        float x0f = fminf(fmaxf(floorf(x), 0.f), (float)(Wl - 1));
        int y0 = (int)y0f, x0 = (int)x0f;
        int y1 = min(y0 + 1, Hl - 1), x1 = min(x0 + 1, Wl - 1);
        float wy = y - y0f, wx = x - x0f;
        int base = b * Hl * Wl;
        int* mo = (int*)(sm + SM_METAO) + tid * 4;
        float* mw = (float*)(sm + SM_METAW) + tid * 4;
        mo[0] = (base + y0 * Wl + x0) * 64;
        mo[1] = (base + y0 * Wl + x1) * 64;
        mo[2] = (base + y1 * Wl + x0) * 64;
        mo[3] = (base + y1 * Wl + x1) * 64;
        mw[0] = (1.f - wy) * (1.f - wx);
        mw[1] = (1.f - wy) * wx;
        mw[2] = wy * (1.f - wx);
        mw[3] = wy * wx;
    }
    __syncthreads();

    float acc[2][8][4];
#pragma unroll
    for (int mt = 0; mt < 2; mt++)
#pragma unroll
        for (int ns = 0; ns < 8; ns++)
#pragma unroll
            for (int i = 0; i < 4; i++) acc[mt][ns][i] = 0.f;

// fp16 single-term KLOOP: per 16-K block: 2 ldmatrix + 8 coalesced LDG.64 + 16 HMMA
#define KLOOP(FRAG, NKB, KB0)                                                    \
    _Pragma("unroll 2")                                                          \
    for (int kbi = 0; kbi < (NKB); kbi++) {                                      \
        uint32_t ah0[4], ah1[4];                                                 \
        uint32_t arow = (uint32_t)(((mrow + (lane & 15)) * KS + kbi * 16 +       \
                                    ((lane >> 4) << 3)) * 2);                    \
        ldm4(ah0, smb + A_HI + arow);                                            \
        ldm4(ah1, smb + A_HI + arow + 16 * KS * 2);                              \
        const uint2* wf = (FRAG) + ((size_t)((KB0) + kbi) * 32 + (ncol >> 3)) * 32 + lane; \
        _Pragma("unroll")                                                        \
        for (int ns = 0; ns < 8; ns++) {                                         \
            uint2 f = __ldg(wf + ns * 32);                                       \
            mma16816(acc[0][ns], ah0, f.x, f.y);                                 \
            mma16816(acc[1][ns], ah1, f.x, f.y);                                 \
        }                                                                        \
    }

    // =================== layer 0: 4 K-chunks ===================
    for (int c = 0; c < 4; c++) {
        if (c < 3) {
            // gather level c -> A[64][256] fp16
            int s = tid >> 2, q = tid & 3;
            const float* lsrc = (c == 0) ? grid : (c == 1 ? g_l1 : g_l2);
            const float4* src = (const float4*)lsrc;
            const int* mo = (const int*)(sm + SM_METAO) + (c * 64 + s) * 4;
            const float* mw = (const float*)(sm + SM_METAW) + (c * 64 + s) * 4;
            int o0 = mo[0], o1 = mo[1], o2 = mo[2], o3 = mo[3];
            float w0v = mw[0], w1v = mw[1], w2v = mw[2], w3v = mw[3];
#pragma unroll
            for (int ch = 0; ch < 16; ch++) {
                int d4 = q * 16 + ch;
                float4 A = __ldg(&src[o0 + d4]);
                float4 B = __ldg(&src[o1 + d4]);
                float4 C = __ldg(&src[o2 + d4]);
                float4 D = __ldg(&src[o3 + d4]);
                float vx = w0v * A.x + w1v * B.x + w2v * C.x + w3v * D.x;
                float vy = w0v * A.y + w1v * B.y + w2v * C.y + w3v * D.y;
                float vz = w0v * A.z + w1v * B.z + w2v * C.z + w3v * D.z;
                float vw = w0v * A.w + w1v * B.w + w2v * C.w + w3v * D.w;
                int off = (s * KS + q * 64 + ch * 4) * 2;
                *(uint2*)(sm + A_HI + off) = make_uint2(pack_h(vx, vy), pack_h(vz, vw));
            }
        } else if (tid < 64) {
            // PE + oracle + zero pad (64 k wide)
            int s = tid, n = n0 + s;
            float a[64];
            float c0v = coords[2 * n], c1v = coords[2 * n + 1];
            a[0] = c0v; a[1] = c1v;
            float pf = 3.14159265358979323846f;
#pragma unroll
            for (int f = 0; f < 10; f++) {
                float s0, q0, s1, q1;
                sincosf(c0v * pf, &s0, &q0);
                sincosf(c1v * pf, &s1, &q1);
                a[2 + 4 * f + 0] = s0; a[2 + 4 * f + 1] = s1;
                a[2 + 4 * f + 2] = q0; a[2 + 4 * f + 3] = q1;
                pf *= 2.0f;
            }
#pragma unroll
            for (int j = 0; j < 3; j++)
                a[42 + j] = oracle[((size_t)b * Nc + n) * 3 + j];
#pragma unroll
            for (int j = 45; j < 64; j++) a[j] = 0.f;
#pragma unroll
            for (int i = 0; i < 16; i++) {
                int off = (s * KS + i * 4) * 2;
                *(uint2*)(sm + A_HI + off) =
                    make_uint2(pack_h(a[4 * i], a[4 * i + 1]), pack_h(a[4 * i + 2], a[4 * i + 3]));
            }
        }
        __syncthreads();
        if (c < 3) { KLOOP(g_w0f, 16, c * 16) }
        else       { KLOOP(g_w0f, 4, 48) }
        __syncthreads();
    }

    // =================== hidden layers ===================
    const float* gam = smf + (SM_GAMMA >> 2);
    const float* bet = smf + (SM_BETA >> 2);
    for (int L = 0; L < 3; L++) {
        const float* bias = smf + (SM_BIAS >> 2) + L * 256;
        // epilogue: gelu(FiLM) in place
#pragma unroll
        for (int mt = 0; mt < 2; mt++)
#pragma unroll
            for (int ns = 0; ns < 8; ns++) {
                int nn0 = ncol + ns * 8 + 2 * t, nn1 = nn0 + 1;
                float ga0 = gam[nn0], ga1 = gam[nn1];
                float be0 = bet[nn0], be1 = bet[nn1];
                float bi0 = bias[nn0], bi1 = bias[nn1];
                acc[mt][ns][0] = gelu_t((acc[mt][ns][0] + bi0) * ga0 + be0);
                acc[mt][ns][1] = gelu_t((acc[mt][ns][1] + bi1) * ga1 + be1);
                acc[mt][ns][2] = gelu_t((acc[mt][ns][2] + bi0) * ga0 + be0);
                acc[mt][ns][3] = gelu_t((acc[mt][ns][3] + bi1) * ga1 + be1);
            }
        __syncthreads();
#pragma unroll
        for (int mt = 0; mt < 2; mt++)
#pragma unroll
            for (int ns = 0; ns < 8; ns++) {
                int nn0 = ncol + ns * 8 + 2 * t;
                int r0 = mrow + mt * 16 + g, r1 = r0 + 8;
                *(uint32_t*)(sm + A_HI + (r0 * KS + nn0) * 2) = pack_h(acc[mt][ns][0], acc[mt][ns][1]);
                *(uint32_t*)(sm + A_HI + (r1 * KS + nn0) * 2) = pack_h(acc[mt][ns][2], acc[mt][ns][3]);
#pragma unroll
                for (int i = 0; i < 4; i++) acc[mt][ns][i] = 0.f;
            }
        __syncthreads();
        KLOOP(g_hwf + (size_t)L * 16384, 16, 0)
    }

    // =================== output layer ===================
    {
        const float* bias = smf + (SM_BIAS >> 2) + 3 * 256;
        const float* oww = smf + (SM_OW >> 2);
        float p[4][3];
#pragma unroll
        for (int i = 0; i < 4; i++) p[i][0] = p[i][1] = p[i][2] = 0.f;
#pragma unroll
        for (int mt = 0; mt < 2; mt++)
#pragma unroll
            for (int ns = 0; ns < 8; ns++) {
                int nn0 = ncol + ns * 8 + 2 * t, nn1 = nn0 + 1;
                float ga0 = gam[nn0], ga1 = gam[nn1];
                float be0 = bet[nn0], be1 = bet[nn1];
                float bi0 = bias[nn0], bi1 = bias[nn1];
                float v0 = gelu_t((acc[mt][ns][0] + bi0) * ga0 + be0);
                float v1 = gelu_t((acc[mt][ns][1] + bi1) * ga1 + be1);
                float v2 = gelu_t((acc[mt][ns][2] + bi0) * ga0 + be0);
                float v3 = gelu_t((acc[mt][ns][3] + bi1) * ga1 + be1);
#pragma unroll
                for (int o = 0; o < 3; o++) {
                    float w0o = oww[nn0 * 3 + o], w1o = oww[nn1 * 3 + o];
                    p[mt * 2 + 0][o] += v0 * w0o + v1 * w1o;
                    p[mt * 2 + 1][o] += v2 * w0o + v3 * w1o;
                }
            }
#pragma unroll
        for (int i = 0; i < 4; i++)
#pragma unroll
            for (int o = 0; o < 3; o++) {
                p[i][o] += __shfl_xor_sync(0xffffffffu, p[i][o], 1);
                p[i][o] += __shfl_xor_sync(0xffffffffu, p[i][o], 2);
            }
        if (t == 0) {
#pragma unroll
            for (int mt = 0; mt < 2; mt++) {
                int r0 = mrow + mt * 16 + g, r1 = r0 + 8;
#pragma unroll
                for (int o = 0; o < 3; o++) {
                    atomicAdd(smf + (SM_PSUM >> 2) + r0 * 3 + o, p[mt * 2 + 0][o]);
                    atomicAdd(smf + (SM_PSUM >> 2) + r1 * 3 + o, p[mt * 2 + 1][o]);
                }
            }
        }
    }
    __syncthreads();
    if (tid < 64) {
        const float* obv = smf + (SM_OW >> 2) + 768;
#pragma unroll
        for (int o = 0; o < 3; o++)
            out[((size_t)b * Nc + n0 + tid) * 3 + o] =
                tanhf(smf[(SM_PSUM >> 2) + tid * 3 + o] + obv[o]);
    }
}

// ---------------- launch ----------------
extern "C" void kernel_launch(void* const* d_in, const int* in_sizes, int n_in,
                              void* d_out, int out_size) {
    const float* grid   = (const float*)d_in[0];
    const float* cv     = (const float*)d_in[1];
    const float* coords = (const float*)d_in[2];
    const float* oracle = (const float*)d_in[3];
    const float* w0     = (const float*)d_in[4];
    const float* b0     = (const float*)d_in[5];
    const float* hw     = (const float*)d_in[6];
    const float* hb     = (const float*)d_in[7];
    const float* cw     = (const float*)d_in[8];
    const float* cb     = (const float*)d_in[9];
    const float* ow     = (const float*)d_in[10];
    const float* ob     = (const float*)d_in[11];
    float* out = (float*)d_out;

    cudaFuncSetAttribute(fused_kernel, cudaFuncAttributeMaxDynamicSharedMemorySize, SM_TOTAL);

    resize2d_l1_kernel<<<(Bc * 64 * 64 * 64 + 255) / 256, 256>>>(grid);
    resize2d_l2_kernel<<<(Bc * 32 * 32 * 64 + 255) / 256, 256>>>(grid);
    film_kernel<<<Bc, 512>>>(cv, cw, cb);
    prep_w0f<<<(52 * 32 * 32 + 255) / 256, 256>>>(w0);
    prep_hwf<<<(3 * 16 * 32 * 32 + 255) / 256, 256>>>(hw);
    fused_kernel<<<Bc * Nc / 64, THREADS, SM_TOTAL>>>(grid, coords, oracle,
                                                      b0, hb, ow, ob, out);
}